// round 4
// baseline (speedup 1.0000x reference)
#include <cuda_runtime.h>
#include <math.h>

#define LSEQ 2048
#define DMODEL 1024
#define NSTATE 32
#define VOCAB 32000
#define CTOT (DMODEL * NSTATE)

// ---------------- scratch (no allocations allowed) ----------------
__device__ float g_xin[LSEQ * DMODEL];
__device__ float g_z[LSEQ * DMODEL];
__device__ float g_delta[LSEQ * DMODEL];
__device__ float g_Bseq[LSEQ * NSTATE];
__device__ float g_Cseq[LSEQ * NSTATE];
__device__ float g_u[LSEQ * DMODEL];
__device__ float g_ln[LSEQ * DMODEL];
__device__ float g_mid[LSEQ * DMODEL];
__device__ float g_y[LSEQ * DMODEL];

// ---------------- tiled SGEMM, software-pipelined: C = A(MxK)*B(NxK)^T + bias ----------------
// MODE 0: plain (+bias)
// MODE 1: split epilogue: col<DMODEL -> C (x_in); col>=DMODEL -> C2 = sigmoid (z)
// MODE 2: softplus(v + bias + bias2)
template <int MODE>
__global__ __launch_bounds__(256) void sgemm_kernel(
    const float* __restrict__ A, const float* __restrict__ B,
    const float* __restrict__ bias, const float* __restrict__ bias2,
    float* __restrict__ C, float* __restrict__ C2,
    int M, int N, int K) {
  __shared__ float As[16][128];
  __shared__ float Bs[16][128];
  const int tid = threadIdx.x;
  const int tx = tid & 15;
  const int ty = tid >> 4;
  const int rowA0 = blockIdx.y * 128;
  const int colB0 = blockIdx.x * 128;

  float acc[8][8];
#pragma unroll
  for (int i = 0; i < 8; i++)
#pragma unroll
    for (int j = 0; j < 8; j++) acc[i][j] = 0.f;

  const int lr = tid >> 2;        // 0..63
  const int lc = (tid & 3) * 4;   // 0,4,8,12

  const float* Ap0 = A + (size_t)(rowA0 + lr) * K + lc;
  const float* Ap1 = A + (size_t)(rowA0 + lr + 64) * K + lc;
  const float* Bp0 = B + (size_t)(colB0 + lr) * K + lc;
  const float* Bp1 = B + (size_t)(colB0 + lr + 64) * K + lc;

  float4 va0 = *(const float4*)(Ap0);
  float4 va1 = *(const float4*)(Ap1);
  float4 vb0 = *(const float4*)(Bp0);
  float4 vb1 = *(const float4*)(Bp1);

  for (int k0 = 0; k0 < K; k0 += 16) {
    As[lc + 0][lr] = va0.x; As[lc + 1][lr] = va0.y;
    As[lc + 2][lr] = va0.z; As[lc + 3][lr] = va0.w;
    As[lc + 0][lr + 64] = va1.x; As[lc + 1][lr + 64] = va1.y;
    As[lc + 2][lr + 64] = va1.z; As[lc + 3][lr + 64] = va1.w;
    Bs[lc + 0][lr] = vb0.x; Bs[lc + 1][lr] = vb0.y;
    Bs[lc + 2][lr] = vb0.z; Bs[lc + 3][lr] = vb0.w;
    Bs[lc + 0][lr + 64] = vb1.x; Bs[lc + 1][lr + 64] = vb1.y;
    Bs[lc + 2][lr + 64] = vb1.z; Bs[lc + 3][lr + 64] = vb1.w;
    __syncthreads();

    if (k0 + 16 < K) {  // prefetch next K-tile while computing
      va0 = *(const float4*)(Ap0 + k0 + 16);
      va1 = *(const float4*)(Ap1 + k0 + 16);
      vb0 = *(const float4*)(Bp0 + k0 + 16);
      vb1 = *(const float4*)(Bp1 + k0 + 16);
    }

#pragma unroll
    for (int kk = 0; kk < 16; kk++) {
      float4 a0 = *(const float4*)&As[kk][ty * 8];
      float4 a1 = *(const float4*)&As[kk][ty * 8 + 4];
      float4 b0 = *(const float4*)&Bs[kk][tx * 8];
      float4 b1 = *(const float4*)&Bs[kk][tx * 8 + 4];
      float av[8] = {a0.x, a0.y, a0.z, a0.w, a1.x, a1.y, a1.z, a1.w};
      float bv[8] = {b0.x, b0.y, b0.z, b0.w, b1.x, b1.y, b1.z, b1.w};
#pragma unroll
      for (int i = 0; i < 8; i++)
#pragma unroll
        for (int j = 0; j < 8; j++)
          acc[i][j] = fmaf(av[i], bv[j], acc[i][j]);
    }
    __syncthreads();
  }

#pragma unroll
  for (int i = 0; i < 8; i++) {
    int row = rowA0 + ty * 8 + i;
#pragma unroll
    for (int j = 0; j < 8; j++) {
      int col = colB0 + tx * 8 + j;
      float v = acc[i][j] + bias[col];
      if (MODE == 0) {
        C[(size_t)row * N + col] = v;
      } else if (MODE == 1) {
        if (col < DMODEL)
          C[(size_t)row * DMODEL + col] = v;
        else
          C2[(size_t)row * DMODEL + (col - DMODEL)] = 1.f / (1.f + expf(-v));
      } else {
        v += bias2[col];
        C[(size_t)row * N + col] = (v > 20.f) ? v : log1pf(expf(v));
      }
    }
  }
}

// ---------------- B_seq / C_seq ----------------
__global__ __launch_bounds__(256) void bc_seq_kernel(
    const float* __restrict__ xin, const float* __restrict__ binj,
    const float* __restrict__ cinj,
    const float* __restrict__ W_B, const float* __restrict__ W_C,
    const float* __restrict__ W_bi, const float* __restrict__ W_ci,
    float* __restrict__ Bseq, float* __restrict__ Cseq) {
  __shared__ float sx[DMODEL], sb[DMODEL], sc[DMODEL];
  const int l = blockIdx.x;
  for (int i = threadIdx.x; i < DMODEL; i += 256) {
    sx[i] = xin[(size_t)l * DMODEL + i];
    sb[i] = binj[(size_t)l * DMODEL + i];
    sc[i] = cinj[(size_t)l * DMODEL + i];
  }
  __syncthreads();
  const int n = threadIdx.x >> 3;
  const int part = threadIdx.x & 7;
  float s1 = 0.f, s2 = 0.f, s3 = 0.f, s4 = 0.f;
  const float* wb = W_B + (size_t)n * DMODEL;
  const float* wc = W_C + (size_t)n * DMODEL;
  const float* wbi = W_bi + (size_t)n * DMODEL;
  const float* wci = W_ci + (size_t)n * DMODEL;
#pragma unroll 8
  for (int i = 0; i < 128; i++) {
    int k = part + i * 8;
    float xv = sx[k], bv = sb[k], cv = sc[k];
    s1 = fmaf(xv, wb[k], s1);
    s2 = fmaf(bv, wbi[k], s2);
    s3 = fmaf(xv, wc[k], s3);
    s4 = fmaf(cv, wci[k], s4);
  }
#pragma unroll
  for (int off = 4; off; off >>= 1) {
    s1 += __shfl_down_sync(0xffffffffu, s1, off, 8);
    s2 += __shfl_down_sync(0xffffffffu, s2, off, 8);
    s3 += __shfl_down_sync(0xffffffffu, s3, off, 8);
    s4 += __shfl_down_sync(0xffffffffu, s4, off, 8);
  }
  if (part == 0) {
    Bseq[(size_t)l * NSTATE + n] = s1 * (1.f + tanhf(s2));
    Cseq[(size_t)l * NSTATE + n] = s3 * (1.f + tanhf(s4));
  }
}

// ---------------- fused exact tree scan ----------------
// One block = one d, 8 n's. Full L=2048 (a,b) series in smem; exact reference
// upsweep / root-reset / downsweep; epilogue reduces h·C over the 8 n's and
// atomicAdds into y[t][d].
#define SCAN_COLS 8
#define SCAN_PITCH 2049  // padded to break bank conflicts
__global__ __launch_bounds__(256, 1) void fused_scan_kernel(
    const float* __restrict__ log_A, const float* __restrict__ delta,
    const float* __restrict__ Bseq, const float* __restrict__ Cseq,
    float* __restrict__ y) {
  extern __shared__ float smem[];
  float* sa = smem;
  float* sb = smem + SCAN_COLS * SCAN_PITCH;

  const int tid = threadIdx.x;
  const int d = blockIdx.x >> 2;
  const int n0 = (blockIdx.x & 3) * 8;

  // init: a[t] = exp(delta[t,d]*A_c); b[t] = (a-1)/A_c * Bseq[t,n]
  {
    const int col = tid & 7;
    const int c = d * NSTATE + n0 + col;
    const float A = -expf(log_A[c]);
    const float invA = 1.f / A;
    const int n = n0 + col;
    int t = tid >> 3;
#pragma unroll 4
    for (int k = 0; k < LSEQ / 32; k++, t += 32) {
      float dt = delta[(size_t)t * DMODEL + d];
      float a = expf(dt * A);
      float b = (a - 1.f) * invA * Bseq[t * NSTATE + n];
      sa[col * SCAN_PITCH + t] = a;
      sb[col * SCAN_PITCH + t] = b;
    }
  }
  __syncthreads();

  // exact reference upsweep
  for (int step = 1; step < LSEQ; step <<= 1) {
    int nit = SCAN_COLS * (LSEQ / (2 * step));
    for (int i = tid; i < nit; i += 256) {
      int col = i & 7;
      int pr = i >> 3;
      int l = pr * 2 * step + step - 1;
      int r = l + step;
      float* pa = sa + col * SCAN_PITCH;
      float* pb = sb + col * SCAN_PITCH;
      float ar = pa[r] * pa[l];
      float br = ar * pb[l] + pb[r];
      pa[r] = ar;
      pb[r] = br;
    }
    __syncthreads();
  }

  // root reset
  if (tid < SCAN_COLS) {
    sa[tid * SCAN_PITCH + (LSEQ - 1)] = 1.f;
    sb[tid * SCAN_PITCH + (LSEQ - 1)] = 0.f;
  }
  __syncthreads();

  // exact reference downsweep
  for (int step = LSEQ >> 1; step >= 1; step >>= 1) {
    int nit = SCAN_COLS * (LSEQ / (2 * step));
    for (int i = tid; i < nit; i += 256) {
      int col = i & 7;
      int pr = i >> 3;
      int l = pr * 2 * step + step - 1;
      int r = l + step;
      float* pa = sa + col * SCAN_PITCH;
      float* pb = sb + col * SCAN_PITCH;
      float al = pa[l], bl = pb[l];
      float ar = pa[r], br = pb[r];
      float nb = ar * bl + br;
      pa[l] = ar;
      pa[r] = ar * al;
      pb[l] = nb;
      pb[r] = nb;
    }
    __syncthreads();
  }

  // epilogue: partial y[t,d] over this block's 8 n's
  for (int t = tid; t < LSEQ; t += 256) {
    float acc = 0.f;
#pragma unroll
    for (int col = 0; col < SCAN_COLS; col++)
      acc = fmaf(sb[col * SCAN_PITCH + t], Cseq[t * NSTATE + n0 + col], acc);
    atomicAdd(&y[(size_t)t * DMODEL + d], acc);
  }
}

// ---------------- u = y*z + x_in ----------------
__global__ __launch_bounds__(256) void u_kernel(
    const float* __restrict__ y, const float* __restrict__ z,
    const float* __restrict__ xin, float* __restrict__ u) {
  size_t i = (size_t)blockIdx.x * 256 + threadIdx.x;
  u[i] = fmaf(y[i], z[i], xin[i]);
}

// ---------------- LayerNorm ----------------
__global__ __launch_bounds__(256) void layernorm_kernel(
    const float* __restrict__ u, const float* __restrict__ g,
    const float* __restrict__ beta, float* __restrict__ o) {
  const int l = blockIdx.x;
  const float* row = u + (size_t)l * DMODEL;
  float s = 0.f, s2 = 0.f;
  for (int i = threadIdx.x; i < DMODEL; i += 256) {
    float v = row[i];
    s += v;
    s2 += v * v;
  }
#pragma unroll
  for (int off = 16; off; off >>= 1) {
    s += __shfl_xor_sync(0xffffffffu, s, off);
    s2 += __shfl_xor_sync(0xffffffffu, s2, off);
  }
  __shared__ float shs[8], shs2[8];
  const int w = threadIdx.x >> 5;
  if ((threadIdx.x & 31) == 0) { shs[w] = s; shs2[w] = s2; }
  __syncthreads();
  if (threadIdx.x < 32) {
    s = (threadIdx.x < 8) ? shs[threadIdx.x] : 0.f;
    s2 = (threadIdx.x < 8) ? shs2[threadIdx.x] : 0.f;
#pragma unroll
    for (int off = 4; off; off >>= 1) {
      s += __shfl_xor_sync(0xffffffffu, s, off);
      s2 += __shfl_xor_sync(0xffffffffu, s2, off);
    }
    if (threadIdx.x == 0) { shs[0] = s; shs2[0] = s2; }
  }
  __syncthreads();
  const float mu = shs[0] * (1.f / DMODEL);
  const float var = shs2[0] * (1.f / DMODEL) - mu * mu;
  const float rstd = rsqrtf(var + 1e-5f);
  for (int i = threadIdx.x; i < DMODEL; i += 256)
    o[(size_t)l * DMODEL + i] = (row[i] - mu) * rstd * g[i] + beta[i];
}

// ---------------- launch ----------------
extern "C" void kernel_launch(void* const* d_in, const int* in_sizes, int n_in,
                              void* d_out, int out_size) {
  const float* x         = (const float*)d_in[0];
  const float* b_inject  = (const float*)d_in[1];
  const float* c_inject  = (const float*)d_in[2];
  const float* W_in      = (const float*)d_in[3];
  const float* b_in      = (const float*)d_in[4];
  const float* log_A     = (const float*)d_in[5];
  const float* W_B       = (const float*)d_in[6];
  const float* W_C       = (const float*)d_in[7];
  const float* W_delta   = (const float*)d_in[8];
  const float* b_delta   = (const float*)d_in[9];
  const float* delta_bias= (const float*)d_in[10];
  const float* W_bi      = (const float*)d_in[11];
  const float* W_ci      = (const float*)d_in[12];
  const float* ln_g      = (const float*)d_in[13];
  const float* ln_b      = (const float*)d_in[14];
  const float* W_out     = (const float*)d_in[15];
  const float* b_out     = (const float*)d_in[16];
  const float* W_vocab   = (const float*)d_in[17];
  const float* b_vocab   = (const float*)d_in[18];
  float* out = (float*)d_out;

  void* p;
  cudaGetSymbolAddress(&p, g_xin);   float* xin   = (float*)p;
  cudaGetSymbolAddress(&p, g_z);     float* zbuf  = (float*)p;
  cudaGetSymbolAddress(&p, g_delta); float* delta = (float*)p;
  cudaGetSymbolAddress(&p, g_Bseq);  float* Bseq  = (float*)p;
  cudaGetSymbolAddress(&p, g_Cseq);  float* Cseq  = (float*)p;
  cudaGetSymbolAddress(&p, g_u);     float* ubuf  = (float*)p;
  cudaGetSymbolAddress(&p, g_ln);    float* lnbuf = (float*)p;
  cudaGetSymbolAddress(&p, g_mid);   float* mid   = (float*)p;
  cudaGetSymbolAddress(&p, g_y);     float* ybuf  = (float*)p;

  const int scan_smem = 2 * SCAN_COLS * SCAN_PITCH * (int)sizeof(float);
  cudaFuncSetAttribute(fused_scan_kernel,
                       cudaFuncAttributeMaxDynamicSharedMemorySize, scan_smem);

  // 1. xz = x @ W_in^T + b_in -> x_in, z=sigmoid
  sgemm_kernel<1><<<dim3(2 * DMODEL / 128, LSEQ / 128), 256>>>(
      x, W_in, b_in, nullptr, xin, zbuf, LSEQ, 2 * DMODEL, DMODEL);
  // 2. delta = softplus(x_in @ W_delta^T + b_delta + delta_bias)
  sgemm_kernel<2><<<dim3(DMODEL / 128, LSEQ / 128), 256>>>(
      xin, W_delta, b_delta, delta_bias, delta, nullptr, LSEQ, DMODEL, DMODEL);
  // 3. B_seq / C_seq
  bc_seq_kernel<<<LSEQ, 256>>>(xin, b_inject, c_inject, W_B, W_C, W_bi, W_ci,
                               Bseq, Cseq);
  // 4. fused exact tree scan -> y
  cudaMemsetAsync(ybuf, 0, (size_t)LSEQ * DMODEL * sizeof(float));
  fused_scan_kernel<<<DMODEL * 4, 256, scan_smem>>>(log_A, delta, Bseq, Cseq,
                                                    ybuf);
  // 5. u = y*z + x_in
  u_kernel<<<LSEQ * DMODEL / 256, 256>>>(ybuf, zbuf, xin, ubuf);
  // 6. LayerNorm
  layernorm_kernel<<<LSEQ, 256>>>(ubuf, ln_g, ln_b, lnbuf);
  // 7. mid = ln @ W_out^T + b_out
  sgemm_kernel<0><<<dim3(DMODEL / 128, LSEQ / 128), 256>>>(
      lnbuf, W_out, b_out, nullptr, mid, nullptr, LSEQ, DMODEL, DMODEL);
  // 8. logits = mid @ W_vocab^T + b_vocab (dominant)
  sgemm_kernel<0><<<dim3(VOCAB / 128, LSEQ / 128), 256>>>(
      mid, W_vocab, b_vocab, nullptr, out, nullptr, LSEQ, VOCAB, DMODEL);
}

// round 6
// speedup vs baseline: 1.7338x; 1.7338x over previous
#include <cuda_runtime.h>
#include <cuda_bf16.h>
#include <math.h>
#include <stdint.h>

#define LSEQ 2048
#define DMODEL 1024
#define NSTATE 32
#define VOCAB 32000

// ---------------- scratch (no allocations allowed) ----------------
__device__ float g_xin[LSEQ * DMODEL];
__device__ float g_z[LSEQ * DMODEL];
__device__ float g_delta[LSEQ * DMODEL];
__device__ float g_Bseq[LSEQ * NSTATE];
__device__ float g_Cseq[LSEQ * NSTATE];
__device__ float g_u[LSEQ * DMODEL];
__device__ float g_ln[LSEQ * DMODEL];
__device__ float g_mid[LSEQ * DMODEL];
__device__ float g_y[LSEQ * DMODEL];
__device__ __nv_bfloat16 g_Whi[(size_t)VOCAB * DMODEL];
__device__ __nv_bfloat16 g_Wlo[(size_t)VOCAB * DMODEL];
__device__ __nv_bfloat16 g_midhi[LSEQ * DMODEL];
__device__ __nv_bfloat16 g_midlo[LSEQ * DMODEL];

// ================= fp32 tiled SGEMM (small GEMMs) =================
template <int MODE>
__global__ __launch_bounds__(256) void sgemm_kernel(
    const float* __restrict__ A, const float* __restrict__ B,
    const float* __restrict__ bias, const float* __restrict__ bias2,
    float* __restrict__ C, float* __restrict__ C2, int M, int N, int K) {
  __shared__ float As[16][128];
  __shared__ float Bs[16][128];
  const int tid = threadIdx.x;
  const int tx = tid & 15;
  const int ty = tid >> 4;
  const int rowA0 = blockIdx.y * 128;
  const int colB0 = blockIdx.x * 128;
  float acc[8][8];
#pragma unroll
  for (int i = 0; i < 8; i++)
#pragma unroll
    for (int j = 0; j < 8; j++) acc[i][j] = 0.f;
  const int lr = tid >> 2;
  const int lc = (tid & 3) * 4;
  const float* Ap0 = A + (size_t)(rowA0 + lr) * K + lc;
  const float* Ap1 = A + (size_t)(rowA0 + lr + 64) * K + lc;
  const float* Bp0 = B + (size_t)(colB0 + lr) * K + lc;
  const float* Bp1 = B + (size_t)(colB0 + lr + 64) * K + lc;
  float4 va0 = *(const float4*)(Ap0);
  float4 va1 = *(const float4*)(Ap1);
  float4 vb0 = *(const float4*)(Bp0);
  float4 vb1 = *(const float4*)(Bp1);
  for (int k0 = 0; k0 < K; k0 += 16) {
    As[lc + 0][lr] = va0.x; As[lc + 1][lr] = va0.y;
    As[lc + 2][lr] = va0.z; As[lc + 3][lr] = va0.w;
    As[lc + 0][lr + 64] = va1.x; As[lc + 1][lr + 64] = va1.y;
    As[lc + 2][lr + 64] = va1.z; As[lc + 3][lr + 64] = va1.w;
    Bs[lc + 0][lr] = vb0.x; Bs[lc + 1][lr] = vb0.y;
    Bs[lc + 2][lr] = vb0.z; Bs[lc + 3][lr] = vb0.w;
    Bs[lc + 0][lr + 64] = vb1.x; Bs[lc + 1][lr + 64] = vb1.y;
    Bs[lc + 2][lr + 64] = vb1.z; Bs[lc + 3][lr + 64] = vb1.w;
    __syncthreads();
    if (k0 + 16 < K) {
      va0 = *(const float4*)(Ap0 + k0 + 16);
      va1 = *(const float4*)(Ap1 + k0 + 16);
      vb0 = *(const float4*)(Bp0 + k0 + 16);
      vb1 = *(const float4*)(Bp1 + k0 + 16);
    }
#pragma unroll
    for (int kk = 0; kk < 16; kk++) {
      float4 a0 = *(const float4*)&As[kk][ty * 8];
      float4 a1 = *(const float4*)&As[kk][ty * 8 + 4];
      float4 b0 = *(const float4*)&Bs[kk][tx * 8];
      float4 b1 = *(const float4*)&Bs[kk][tx * 8 + 4];
      float av[8] = {a0.x, a0.y, a0.z, a0.w, a1.x, a1.y, a1.z, a1.w};
      float bv[8] = {b0.x, b0.y, b0.z, b0.w, b1.x, b1.y, b1.z, b1.w};
#pragma unroll
      for (int i = 0; i < 8; i++)
#pragma unroll
        for (int j = 0; j < 8; j++) acc[i][j] = fmaf(av[i], bv[j], acc[i][j]);
    }
    __syncthreads();
  }
#pragma unroll
  for (int i = 0; i < 8; i++) {
    int row = rowA0 + ty * 8 + i;
#pragma unroll
    for (int j = 0; j < 8; j++) {
      int col = colB0 + tx * 8 + j;
      float v = acc[i][j] + bias[col];
      if (MODE == 0) {
        C[(size_t)row * N + col] = v;
      } else if (MODE == 1) {
        if (col < DMODEL)
          C[(size_t)row * DMODEL + col] = v;
        else
          C2[(size_t)row * DMODEL + (col - DMODEL)] = 1.f / (1.f + expf(-v));
      } else {
        v += bias2[col];
        C[(size_t)row * N + col] = (v > 20.f) ? v : log1pf(expf(v));
      }
    }
  }
}

// ================= bf16 hi/lo split conversion =================
__global__ __launch_bounds__(256) void split_kernel(
    const float* __restrict__ src, __nv_bfloat16* __restrict__ hi,
    __nv_bfloat16* __restrict__ lo, int n4) {
  int i = blockIdx.x * 256 + threadIdx.x;
  if (i >= n4) return;
  float4 v = ((const float4*)src)[i];
  float vv[4] = {v.x, v.y, v.z, v.w};
  union { __nv_bfloat16 b[4]; uint2 u; } H, L;
#pragma unroll
  for (int j = 0; j < 4; j++) {
    __nv_bfloat16 h = __float2bfloat16(vv[j]);
    H.b[j] = h;
    L.b[j] = __float2bfloat16(vv[j] - __bfloat162float(h));
  }
  ((uint2*)hi)[i] = H.u;
  ((uint2*)lo)[i] = L.u;
}

// ================= bf16x3 GEMM via mma.sync (base ISA, works on sm_103) =====
// out(MxN) = A(MxK) * B(NxK)^T + bias;  A=Ahi+Alo, B=Bhi+Blo, 3 products.
// Block 128x128, K-chunk 32, 8 warps (2x4), warp tile 64x32.
// Smem row stride 20 words (16 data + 4 pad) -> conflict-free fragment LDS.
#define SROW 20

__device__ __forceinline__ void mma16816(float* c, const uint32_t* a,
                                         const uint32_t* b) {
  asm volatile(
      "mma.sync.aligned.m16n8k16.row.col.f32.bf16.bf16.f32 "
      "{%0,%1,%2,%3}, {%4,%5,%6,%7}, {%8,%9}, {%0,%1,%2,%3};"
      : "+f"(c[0]), "+f"(c[1]), "+f"(c[2]), "+f"(c[3])
      : "r"(a[0]), "r"(a[1]), "r"(a[2]), "r"(a[3]), "r"(b[0]), "r"(b[1]));
}

__global__ __launch_bounds__(256, 1) void mma_gemm_kernel(
    const __nv_bfloat16* __restrict__ Ahi, const __nv_bfloat16* __restrict__ Alo,
    const __nv_bfloat16* __restrict__ Bhi, const __nv_bfloat16* __restrict__ Blo,
    const float* __restrict__ bias, float* __restrict__ out, int Ncols) {
  __shared__ uint32_t sm[4 * 128 * SROW];
  uint32_t* sAh = sm;
  uint32_t* sAl = sm + 128 * SROW;
  uint32_t* sBh = sm + 2 * 128 * SROW;
  uint32_t* sBl = sm + 3 * 128 * SROW;

  const int tid = threadIdx.x;
  const int wid = tid >> 5, lane = tid & 31;
  const int wr = wid >> 2, wc = wid & 3;
  const int m0 = blockIdx.x * 128, n0 = blockIdx.y * 128;
  const int lr = lane >> 2, lq = lane & 3;

  float acc[4][4][4];
#pragma unroll
  for (int i = 0; i < 4; i++)
#pragma unroll
    for (int j = 0; j < 4; j++)
#pragma unroll
      for (int q = 0; q < 4; q++) acc[i][j][q] = 0.f;

  // per-thread load slots: rows r0 and r0+64, uint4 q0 within row
  const int r0 = tid >> 2, q0 = tid & 3;
  const __nv_bfloat16* gp[8] = {
      Ahi + (size_t)(m0 + r0) * DMODEL + q0 * 8,
      Ahi + (size_t)(m0 + r0 + 64) * DMODEL + q0 * 8,
      Alo + (size_t)(m0 + r0) * DMODEL + q0 * 8,
      Alo + (size_t)(m0 + r0 + 64) * DMODEL + q0 * 8,
      Bhi + (size_t)(n0 + r0) * DMODEL + q0 * 8,
      Bhi + (size_t)(n0 + r0 + 64) * DMODEL + q0 * 8,
      Blo + (size_t)(n0 + r0) * DMODEL + q0 * 8,
      Blo + (size_t)(n0 + r0 + 64) * DMODEL + q0 * 8};
  uint32_t* sp[8] = {
      sAh + r0 * SROW + q0 * 4,        sAh + (r0 + 64) * SROW + q0 * 4,
      sAl + r0 * SROW + q0 * 4,        sAl + (r0 + 64) * SROW + q0 * 4,
      sBh + r0 * SROW + q0 * 4,        sBh + (r0 + 64) * SROW + q0 * 4,
      sBl + r0 * SROW + q0 * 4,        sBl + (r0 + 64) * SROW + q0 * 4};

  uint4 pf[8];
#pragma unroll
  for (int t = 0; t < 8; t++) pf[t] = *(const uint4*)(gp[t]);

  for (int chunk = 0; chunk < DMODEL / 32; chunk++) {
#pragma unroll
    for (int t = 0; t < 8; t++) *(uint4*)(sp[t]) = pf[t];
    __syncthreads();
    if (chunk + 1 < DMODEL / 32) {
      const int k1 = (chunk + 1) * 32;
#pragma unroll
      for (int t = 0; t < 8; t++) pf[t] = *(const uint4*)(gp[t] + k1);
    }
#pragma unroll
    for (int s = 0; s < 2; s++) {
      const int kw = s * 8 + lq;
      uint32_t ah[4][4], al[4][4], bh[4][2], bl[4][2];
#pragma unroll
      for (int i = 0; i < 4; i++) {
        int base = (wr * 64 + i * 16 + lr) * SROW + kw;
        ah[i][0] = sAh[base];            ah[i][1] = sAh[base + 8 * SROW];
        ah[i][2] = sAh[base + 4];        ah[i][3] = sAh[base + 8 * SROW + 4];
        al[i][0] = sAl[base];            al[i][1] = sAl[base + 8 * SROW];
        al[i][2] = sAl[base + 4];        al[i][3] = sAl[base + 8 * SROW + 4];
      }
#pragma unroll
      for (int j = 0; j < 4; j++) {
        int base = (wc * 32 + j * 8 + lr) * SROW + kw;
        bh[j][0] = sBh[base];  bh[j][1] = sBh[base + 4];
        bl[j][0] = sBl[base];  bl[j][1] = sBl[base + 4];
      }
#pragma unroll
      for (int i = 0; i < 4; i++)
#pragma unroll
        for (int j = 0; j < 4; j++) {
          mma16816(acc[i][j], ah[i], bh[j]);
          mma16816(acc[i][j], ah[i], bl[j]);
          mma16816(acc[i][j], al[i], bh[j]);
        }
    }
    __syncthreads();
  }

  // epilogue
#pragma unroll
  for (int i = 0; i < 4; i++) {
    const int r = m0 + wr * 64 + i * 16 + lr;
#pragma unroll
    for (int j = 0; j < 4; j++) {
      const int c = n0 + wc * 32 + j * 8 + lq * 2;
      const float bx = bias[c], by = bias[c + 1];
      float2 v0 = {acc[i][j][0] + bx, acc[i][j][1] + by};
      float2 v1 = {acc[i][j][2] + bx, acc[i][j][3] + by};
      *(float2*)(out + (size_t)r * Ncols + c) = v0;
      *(float2*)(out + (size_t)(r + 8) * Ncols + c) = v1;
    }
  }
}

// ================= B_seq / C_seq =================
__global__ __launch_bounds__(256) void bc_seq_kernel(
    const float* __restrict__ xin, const float* __restrict__ binj,
    const float* __restrict__ cinj, const float* __restrict__ W_B,
    const float* __restrict__ W_C, const float* __restrict__ W_bi,
    const float* __restrict__ W_ci, float* __restrict__ Bseq,
    float* __restrict__ Cseq) {
  __shared__ float sx[DMODEL], sb[DMODEL], sc[DMODEL];
  const int l = blockIdx.x;
  for (int i = threadIdx.x; i < DMODEL; i += 256) {
    sx[i] = xin[(size_t)l * DMODEL + i];
    sb[i] = binj[(size_t)l * DMODEL + i];
    sc[i] = cinj[(size_t)l * DMODEL + i];
  }
  __syncthreads();
  const int n = threadIdx.x >> 3;
  const int part = threadIdx.x & 7;
  float s1 = 0.f, s2 = 0.f, s3 = 0.f, s4 = 0.f;
  const float* wb = W_B + (size_t)n * DMODEL;
  const float* wc = W_C + (size_t)n * DMODEL;
  const float* wbi = W_bi + (size_t)n * DMODEL;
  const float* wci = W_ci + (size_t)n * DMODEL;
#pragma unroll 8
  for (int i = 0; i < 128; i++) {
    int k = part + i * 8;
    float xv = sx[k], bv = sb[k], cv = sc[k];
    s1 = fmaf(xv, wb[k], s1);
    s2 = fmaf(bv, wbi[k], s2);
    s3 = fmaf(xv, wc[k], s3);
    s4 = fmaf(cv, wci[k], s4);
  }
#pragma unroll
  for (int off = 4; off; off >>= 1) {
    s1 += __shfl_down_sync(0xffffffffu, s1, off, 8);
    s2 += __shfl_down_sync(0xffffffffu, s2, off, 8);
    s3 += __shfl_down_sync(0xffffffffu, s3, off, 8);
    s4 += __shfl_down_sync(0xffffffffu, s4, off, 8);
  }
  if (part == 0) {
    Bseq[(size_t)l * NSTATE + n] = s1 * (1.f + tanhf(s2));
    Cseq[(size_t)l * NSTATE + n] = s3 * (1.f + tanhf(s4));
  }
}

// ================= fused exact tree scan (fast-exp init) =================
#define SCAN_COLS 8
#define SCAN_PITCH 2049
__global__ __launch_bounds__(256, 1) void fused_scan_kernel(
    const float* __restrict__ log_A, const float* __restrict__ delta,
    const float* __restrict__ Bseq, const float* __restrict__ Cseq,
    float* __restrict__ y) {
  extern __shared__ float smem[];
  float* sa = smem;
  float* sb = smem + SCAN_COLS * SCAN_PITCH;
  __shared__ float sS[8], sInv[8];
  __shared__ int sOk[8];

  const int tid = threadIdx.x;
  const int d = blockIdx.x >> 2;
  const int n0 = (blockIdx.x & 3) * 8;

  if (tid < 8) {
    float s = expf(log_A[d * NSTATE + n0 + tid]);
    sS[tid] = s;
    sInv[tid] = 1.f / s;
    sOk[tid] = fabsf(s - (float)(n0 + tid + 1)) < 1e-3f ? 1 : 0;
  }
  __syncthreads();
  const bool fast = sOk[0] && sOk[1] && sOk[2] && sOk[3] && sOk[4] && sOk[5] &&
                    sOk[6] && sOk[7];

  for (int t = tid; t < LSEQ; t += 256) {
    float dt = delta[(size_t)t * DMODEL + d];
    float4 b0 = *(const float4*)(Bseq + t * NSTATE + n0);
    float4 b1 = *(const float4*)(Bseq + t * NSTATE + n0 + 4);
    float bs[8] = {b0.x, b0.y, b0.z, b0.w, b1.x, b1.y, b1.z, b1.w};
    if (fast) {
      float E = expf(-dt);
      float e2 = E * E, e4 = e2 * e2, e8 = e4 * e4;
      float p = (n0 == 0) ? 1.f
                : (n0 == 8) ? e8
                : (n0 == 16) ? e8 * e8 : (e8 * e8) * e8;
#pragma unroll
      for (int c = 0; c < 8; c++) {
        p *= E;  // p = E^(n0+c+1) = exp(dt*A)
        sa[c * SCAN_PITCH + t] = p;
        sb[c * SCAN_PITCH + t] = (1.f - p) * sInv[c] * bs[c];
      }
    } else {
#pragma unroll
      for (int c = 0; c < 8; c++) {
        float a = expf(-dt * sS[c]);
        sa[c * SCAN_PITCH + t] = a;
        sb[c * SCAN_PITCH + t] = (1.f - a) * sInv[c] * bs[c];
      }
    }
  }
  __syncthreads();

  for (int step = 1; step < LSEQ; step <<= 1) {
    int nit = SCAN_COLS * (LSEQ / (2 * step));
    for (int i = tid; i < nit; i += 256) {
      int col = i & 7;
      int pr = i >> 3;
      int l = pr * 2 * step + step - 1;
      int r = l + step;
      float* pa = sa + col * SCAN_PITCH;
      float* pb = sb + col * SCAN_PITCH;
      float ar = pa[r] * pa[l];
      float br = ar * pb[l] + pb[r];
      pa[r] = ar;
      pb[r] = br;
    }
    __syncthreads();
  }
  if (tid < SCAN_COLS) {
    sa[tid * SCAN_PITCH + (LSEQ - 1)] = 1.f;
    sb[tid * SCAN_PITCH + (LSEQ - 1)] = 0.f;
  }
  __syncthreads();
  for (int step = LSEQ >> 1; step >= 1; step >>= 1) {
    int nit = SCAN_COLS * (LSEQ / (2 * step));
    for (int i = tid; i < nit; i += 256) {
      int col = i & 7;
      int pr = i >> 3;
      int l = pr * 2 * step + step - 1;
      int r = l + step;
      float* pa = sa + col * SCAN_PITCH;
      float* pb = sb + col * SCAN_PITCH;
      float al = pa[l], bl = pb[l];
      float ar = pa[r], br = pb[r];
      float nb = ar * bl + br;
      pa[l] = ar;
      pa[r] = ar * al;
      pb[l] = nb;
      pb[r] = nb;
    }
    __syncthreads();
  }
  for (int t = tid; t < LSEQ; t += 256) {
    float acc = 0.f;
#pragma unroll
    for (int col = 0; col < SCAN_COLS; col++)
      acc = fmaf(sb[col * SCAN_PITCH + t], Cseq[t * NSTATE + n0 + col], acc);
    atomicAdd(&y[(size_t)t * DMODEL + d], acc);
  }
}

// ================= u = y*z + x_in =================
__global__ __launch_bounds__(256) void u_kernel(const float* __restrict__ y,
                                                const float* __restrict__ z,
                                                const float* __restrict__ xin,
                                                float* __restrict__ u) {
  size_t i = (size_t)blockIdx.x * 256 + threadIdx.x;
  u[i] = fmaf(y[i], z[i], xin[i]);
}

// ================= LayerNorm =================
__global__ __launch_bounds__(256) void layernorm_kernel(
    const float* __restrict__ u, const float* __restrict__ g,
    const float* __restrict__ beta, float* __restrict__ o) {
  const int l = blockIdx.x;
  const float* row = u + (size_t)l * DMODEL;
  float s = 0.f, s2 = 0.f;
  for (int i = threadIdx.x; i < DMODEL; i += 256) {
    float v = row[i];
    s += v;
    s2 += v * v;
  }
#pragma unroll
  for (int off = 16; off; off >>= 1) {
    s += __shfl_xor_sync(0xffffffffu, s, off);
    s2 += __shfl_xor_sync(0xffffffffu, s2, off);
  }
  __shared__ float shs[8], shs2[8];
  const int w = threadIdx.x >> 5;
  if ((threadIdx.x & 31) == 0) { shs[w] = s; shs2[w] = s2; }
  __syncthreads();
  if (threadIdx.x < 32) {
    s = (threadIdx.x < 8) ? shs[threadIdx.x] : 0.f;
    s2 = (threadIdx.x < 8) ? shs2[threadIdx.x] : 0.f;
#pragma unroll
    for (int off = 4; off; off >>= 1) {
      s += __shfl_xor_sync(0xffffffffu, s, off);
      s2 += __shfl_xor_sync(0xffffffffu, s2, off);
    }
    if (threadIdx.x == 0) { shs[0] = s; shs2[0] = s2; }
  }
  __syncthreads();
  const float mu = shs[0] * (1.f / DMODEL);
  const float var = shs2[0] * (1.f / DMODEL) - mu * mu;
  const float rstd = rsqrtf(var + 1e-5f);
  for (int i = threadIdx.x; i < DMODEL; i += 256)
    o[(size_t)l * DMODEL + i] = (row[i] - mu) * rstd * g[i] + beta[i];
}

// ================= launch =================
extern "C" void kernel_launch(void* const* d_in, const int* in_sizes, int n_in,
                              void* d_out, int out_size) {
  const float* x         = (const float*)d_in[0];
  const float* b_inject  = (const float*)d_in[1];
  const float* c_inject  = (const float*)d_in[2];
  const float* W_in      = (const float*)d_in[3];
  const float* b_in      = (const float*)d_in[4];
  const float* log_A     = (const float*)d_in[5];
  const float* W_B       = (const float*)d_in[6];
  const float* W_C       = (const float*)d_in[7];
  const float* W_delta   = (const float*)d_in[8];
  const float* b_delta   = (const float*)d_in[9];
  const float* delta_bias= (const float*)d_in[10];
  const float* W_bi      = (const float*)d_in[11];
  const float* W_ci      = (const float*)d_in[12];
  const float* ln_g      = (const float*)d_in[13];
  const float* ln_b      = (const float*)d_in[14];
  const float* W_out     = (const float*)d_in[15];
  const float* b_out     = (const float*)d_in[16];
  const float* W_vocab   = (const float*)d_in[17];
  const float* b_vocab   = (const float*)d_in[18];
  float* out = (float*)d_out;

  void* p;
  cudaGetSymbolAddress(&p, g_xin);   float* xin   = (float*)p;
  cudaGetSymbolAddress(&p, g_z);     float* zbuf  = (float*)p;
  cudaGetSymbolAddress(&p, g_delta); float* delta = (float*)p;
  cudaGetSymbolAddress(&p, g_Bseq);  float* Bseq  = (float*)p;
  cudaGetSymbolAddress(&p, g_Cseq);  float* Cseq  = (float*)p;
  cudaGetSymbolAddress(&p, g_u);     float* ubuf  = (float*)p;
  cudaGetSymbolAddress(&p, g_ln);    float* lnbuf = (float*)p;
  cudaGetSymbolAddress(&p, g_mid);   float* mid   = (float*)p;
  cudaGetSymbolAddress(&p, g_y);     float* ybuf  = (float*)p;
  cudaGetSymbolAddress(&p, g_Whi);   __nv_bfloat16* whi = (__nv_bfloat16*)p;
  cudaGetSymbolAddress(&p, g_Wlo);   __nv_bfloat16* wlo = (__nv_bfloat16*)p;
  cudaGetSymbolAddress(&p, g_midhi); __nv_bfloat16* mhi = (__nv_bfloat16*)p;
  cudaGetSymbolAddress(&p, g_midlo); __nv_bfloat16* mlo = (__nv_bfloat16*)p;

  const int scan_smem = 2 * SCAN_COLS * SCAN_PITCH * (int)sizeof(float);
  cudaFuncSetAttribute(fused_scan_kernel,
                       cudaFuncAttributeMaxDynamicSharedMemorySize, scan_smem);

  // 1. xz = x @ W_in^T + b_in -> x_in, z
  sgemm_kernel<1><<<dim3(2 * DMODEL / 128, LSEQ / 128), 256>>>(
      x, W_in, b_in, nullptr, xin, zbuf, LSEQ, 2 * DMODEL, DMODEL);
  // 2. delta
  sgemm_kernel<2><<<dim3(DMODEL / 128, LSEQ / 128), 256>>>(
      xin, W_delta, b_delta, delta_bias, delta, nullptr, LSEQ, DMODEL, DMODEL);
  // 3. B_seq / C_seq
  bc_seq_kernel<<<LSEQ, 256>>>(xin, b_inject, c_inject, W_B, W_C, W_bi, W_ci,
                               Bseq, Cseq);
  // 4. scan -> y
  cudaMemsetAsync(ybuf, 0, (size_t)LSEQ * DMODEL * sizeof(float));
  fused_scan_kernel<<<DMODEL * 4, 256, scan_smem>>>(log_A, delta, Bseq, Cseq,
                                                    ybuf);
  // 5. u = y*z + x_in
  u_kernel<<<LSEQ * DMODEL / 256, 256>>>(ybuf, zbuf, xin, ubuf);
  // 6. LayerNorm
  layernorm_kernel<<<LSEQ, 256>>>(ubuf, ln_g, ln_b, lnbuf);
  // 7. mid = ln @ W_out^T + b_out
  sgemm_kernel<0><<<dim3(DMODEL / 128, LSEQ / 128), 256>>>(
      lnbuf, W_out, b_out, nullptr, mid, nullptr, LSEQ, DMODEL, DMODEL);
  // 8. split conversions (W_vocab split is the big one: ~260MB traffic)
  split_kernel<<<(LSEQ * DMODEL / 4 + 255) / 256, 256>>>(mid, mhi, mlo,
                                                         LSEQ * DMODEL / 4);
  split_kernel<<<((int)((size_t)VOCAB * DMODEL / 4) + 255) / 256, 256>>>(
      W_vocab, whi, wlo, (int)((size_t)VOCAB * DMODEL / 4));
  // 9. logits = mid @ W_vocab^T + b_vocab  (bf16x3 mma.sync)
  mma_gemm_kernel<<<dim3(LSEQ / 128, VOCAB / 128), 256>>>(mhi, mlo, whi, wlo,
                                                          b_vocab, out, VOCAB);
}

// round 9
// speedup vs baseline: 1.8564x; 1.0708x over previous
#include <cuda_runtime.h>
#include <cuda_bf16.h>
#include <math.h>
#include <stdint.h>

#define LSEQ 2048
#define DMODEL 1024
#define NSTATE 32
#define VOCAB 32000

// ---------------- scratch (no allocations allowed) ----------------
__device__ float g_xin[LSEQ * DMODEL];
__device__ float g_z[LSEQ * DMODEL];
__device__ float g_delta[LSEQ * DMODEL];
__device__ float g_Bseq[LSEQ * NSTATE];
__device__ float g_Cseq[LSEQ * NSTATE];
__device__ float g_u[LSEQ * DMODEL];
__device__ float g_ln[LSEQ * DMODEL];
__device__ float g_mid[LSEQ * DMODEL];
__device__ float g_y[LSEQ * DMODEL];
__device__ __nv_bfloat16 g_Whi[(size_t)VOCAB * DMODEL];
__device__ __nv_bfloat16 g_Wlo[(size_t)VOCAB * DMODEL];
__device__ __nv_bfloat16 g_midhi[LSEQ * DMODEL];
__device__ __nv_bfloat16 g_midlo[LSEQ * DMODEL];

__device__ __forceinline__ uint32_t smem_u32(const void* p) {
  uint32_t a;
  asm("{ .reg .u64 t; cvta.to.shared.u64 t, %1; cvt.u32.u64 %0, t; }"
      : "=r"(a) : "l"(p));
  return a;
}

// ================= fp32 tiled SGEMM (small GEMMs) =================
template <int MODE>
__global__ __launch_bounds__(256) void sgemm_kernel(
    const float* __restrict__ A, const float* __restrict__ B,
    const float* __restrict__ bias, const float* __restrict__ bias2,
    float* __restrict__ C, float* __restrict__ C2, int M, int N, int K) {
  __shared__ float As[16][128];
  __shared__ float Bs[16][128];
  const int tid = threadIdx.x;
  const int tx = tid & 15;
  const int ty = tid >> 4;
  const int rowA0 = blockIdx.y * 128;
  const int colB0 = blockIdx.x * 128;
  float acc[8][8];
#pragma unroll
  for (int i = 0; i < 8; i++)
#pragma unroll
    for (int j = 0; j < 8; j++) acc[i][j] = 0.f;
  const int lr = tid >> 2;
  const int lc = (tid & 3) * 4;
  const float* Ap0 = A + (size_t)(rowA0 + lr) * K + lc;
  const float* Ap1 = A + (size_t)(rowA0 + lr + 64) * K + lc;
  const float* Bp0 = B + (size_t)(colB0 + lr) * K + lc;
  const float* Bp1 = B + (size_t)(colB0 + lr + 64) * K + lc;
  float4 va0 = *(const float4*)(Ap0);
  float4 va1 = *(const float4*)(Ap1);
  float4 vb0 = *(const float4*)(Bp0);
  float4 vb1 = *(const float4*)(Bp1);
  for (int k0 = 0; k0 < K; k0 += 16) {
    As[lc + 0][lr] = va0.x; As[lc + 1][lr] = va0.y;
    As[lc + 2][lr] = va0.z; As[lc + 3][lr] = va0.w;
    As[lc + 0][lr + 64] = va1.x; As[lc + 1][lr + 64] = va1.y;
    As[lc + 2][lr + 64] = va1.z; As[lc + 3][lr + 64] = va1.w;
    Bs[lc + 0][lr] = vb0.x; Bs[lc + 1][lr] = vb0.y;
    Bs[lc + 2][lr] = vb0.z; Bs[lc + 3][lr] = vb0.w;
    Bs[lc + 0][lr + 64] = vb1.x; Bs[lc + 1][lr + 64] = vb1.y;
    Bs[lc + 2][lr + 64] = vb1.z; Bs[lc + 3][lr + 64] = vb1.w;
    __syncthreads();
    if (k0 + 16 < K) {
      va0 = *(const float4*)(Ap0 + k0 + 16);
      va1 = *(const float4*)(Ap1 + k0 + 16);
      vb0 = *(const float4*)(Bp0 + k0 + 16);
      vb1 = *(const float4*)(Bp1 + k0 + 16);
    }
#pragma unroll
    for (int kk = 0; kk < 16; kk++) {
      float4 a0 = *(const float4*)&As[kk][ty * 8];
      float4 a1 = *(const float4*)&As[kk][ty * 8 + 4];
      float4 b0 = *(const float4*)&Bs[kk][tx * 8];
      float4 b1 = *(const float4*)&Bs[kk][tx * 8 + 4];
      float av[8] = {a0.x, a0.y, a0.z, a0.w, a1.x, a1.y, a1.z, a1.w};
      float bv[8] = {b0.x, b0.y, b0.z, b0.w, b1.x, b1.y, b1.z, b1.w};
#pragma unroll
      for (int i = 0; i < 8; i++)
#pragma unroll
        for (int j = 0; j < 8; j++) acc[i][j] = fmaf(av[i], bv[j], acc[i][j]);
    }
    __syncthreads();
  }
#pragma unroll
  for (int i = 0; i < 8; i++) {
    int row = rowA0 + ty * 8 + i;
#pragma unroll
    for (int j = 0; j < 8; j++) {
      int col = colB0 + tx * 8 + j;
      float v = acc[i][j] + bias[col];
      if (MODE == 0) {
        C[(size_t)row * N + col] = v;
      } else if (MODE == 1) {
        if (col < DMODEL)
          C[(size_t)row * DMODEL + col] = v;
        else
          C2[(size_t)row * DMODEL + (col - DMODEL)] = 1.f / (1.f + expf(-v));
      } else {
        v += bias2[col];
        C[(size_t)row * N + col] = (v > 20.f) ? v : log1pf(expf(v));
      }
    }
  }
}

// ================= bf16 hi/lo split conversion =================
__global__ __launch_bounds__(256) void split_kernel(
    const float* __restrict__ src, __nv_bfloat16* __restrict__ hi,
    __nv_bfloat16* __restrict__ lo, int n4) {
  int i = blockIdx.x * 256 + threadIdx.x;
  if (i >= n4) return;
  float4 v = ((const float4*)src)[i];
  float vv[4] = {v.x, v.y, v.z, v.w};
  union { __nv_bfloat16 b[4]; uint2 u; } H, L;
#pragma unroll
  for (int j = 0; j < 4; j++) {
    __nv_bfloat16 h = __float2bfloat16(vv[j]);
    H.b[j] = h;
    L.b[j] = __float2bfloat16(vv[j] - __bfloat162float(h));
  }
  ((uint2*)hi)[i] = H.u;
  ((uint2*)lo)[i] = L.u;
}

// ================= bf16x3 GEMM via mma.sync + ldmatrix =====
// out(MxN) = A(MxK) * B(NxK)^T + bias;  3 products (AhBh + AhBl + AlBh).
// Block 128x128, K-chunk 32, 8 warps (2x4), warp tile 64x32.
// Smem row stride 20 words: ldmatrix rows (16B) tile all 32 banks.
#define SROW 20

__device__ __forceinline__ void mma16816(float* c, const uint32_t* a,
                                         const uint32_t* b) {
  asm volatile(
      "mma.sync.aligned.m16n8k16.row.col.f32.bf16.bf16.f32 "
      "{%0,%1,%2,%3}, {%4,%5,%6,%7}, {%8,%9}, {%0,%1,%2,%3};"
      : "+f"(c[0]), "+f"(c[1]), "+f"(c[2]), "+f"(c[3])
      : "r"(a[0]), "r"(a[1]), "r"(a[2]), "r"(a[3]), "r"(b[0]), "r"(b[1]));
}
__device__ __forceinline__ void ldsm_x4(uint32_t* r, uint32_t addr) {
  asm volatile(
      "ldmatrix.sync.aligned.m8n8.x4.shared.b16 {%0,%1,%2,%3}, [%4];"
      : "=r"(r[0]), "=r"(r[1]), "=r"(r[2]), "=r"(r[3]) : "r"(addr));
}
__device__ __forceinline__ void ldsm_x2(uint32_t* r, uint32_t addr) {
  asm volatile(
      "ldmatrix.sync.aligned.m8n8.x2.shared.b16 {%0,%1}, [%2];"
      : "=r"(r[0]), "=r"(r[1]) : "r"(addr));
}

__global__ __launch_bounds__(256, 1) void mma_gemm_kernel(
    const __nv_bfloat16* __restrict__ Ahi, const __nv_bfloat16* __restrict__ Alo,
    const __nv_bfloat16* __restrict__ Bhi, const __nv_bfloat16* __restrict__ Blo,
    const float* __restrict__ bias, float* __restrict__ out, int Ncols) {
  __shared__ uint32_t sm[4 * 128 * SROW];
  uint32_t* sAh = sm;
  uint32_t* sAl = sm + 128 * SROW;
  uint32_t* sBh = sm + 2 * 128 * SROW;
  uint32_t* sBl = sm + 3 * 128 * SROW;
  const uint32_t sb = smem_u32(sm);
  const uint32_t bAh = sb, bAl = sb + 128 * SROW * 4,
                 bBh = sb + 2 * 128 * SROW * 4, bBl = sb + 3 * 128 * SROW * 4;

  const int tid = threadIdx.x;
  const int wid = tid >> 5, lane = tid & 31;
  const int wr = wid >> 2, wc = wid & 3;
  const int m0 = blockIdx.x * 128, n0 = blockIdx.y * 128;
  const int lr = lane >> 2, lq = lane & 3;

  float acc[4][4][4];
#pragma unroll
  for (int i = 0; i < 4; i++)
#pragma unroll
    for (int j = 0; j < 4; j++)
#pragma unroll
      for (int q = 0; q < 4; q++) acc[i][j][q] = 0.f;

  const int r0 = tid >> 2, q0 = tid & 3;
  const __nv_bfloat16* gp[8] = {
      Ahi + (size_t)(m0 + r0) * DMODEL + q0 * 8,
      Ahi + (size_t)(m0 + r0 + 64) * DMODEL + q0 * 8,
      Alo + (size_t)(m0 + r0) * DMODEL + q0 * 8,
      Alo + (size_t)(m0 + r0 + 64) * DMODEL + q0 * 8,
      Bhi + (size_t)(n0 + r0) * DMODEL + q0 * 8,
      Bhi + (size_t)(n0 + r0 + 64) * DMODEL + q0 * 8,
      Blo + (size_t)(n0 + r0) * DMODEL + q0 * 8,
      Blo + (size_t)(n0 + r0 + 64) * DMODEL + q0 * 8};
  uint32_t* sp[8] = {
      sAh + r0 * SROW + q0 * 4,        sAh + (r0 + 64) * SROW + q0 * 4,
      sAl + r0 * SROW + q0 * 4,        sAl + (r0 + 64) * SROW + q0 * 4,
      sBh + r0 * SROW + q0 * 4,        sBh + (r0 + 64) * SROW + q0 * 4,
      sBl + r0 * SROW + q0 * 4,        sBl + (r0 + 64) * SROW + q0 * 4};

  // ldmatrix lane-address components
  const int ag = lane >> 3, ar8 = lane & 7;          // A: 4 groups
  const int aRowOff = (ag & 1) * 8 + ar8;            // +m
  const int aKWord = (ag >> 1) * 4;                  // +k8 -> +4 words
  const int bg = (lane >> 3) & 1;                    // B: groups 0/1 (lanes 0-15)
  const int bRow = lane & 7;
  const int bKWord = bg * 4;

  uint4 pf[8];
#pragma unroll
  for (int t = 0; t < 8; t++) pf[t] = *(const uint4*)(gp[t]);

  for (int chunk = 0; chunk < DMODEL / 32; chunk++) {
#pragma unroll
    for (int t = 0; t < 8; t++) *(uint4*)(sp[t]) = pf[t];
    __syncthreads();
    if (chunk + 1 < DMODEL / 32) {
      const int k1 = (chunk + 1) * 32;
#pragma unroll
      for (int t = 0; t < 8; t++) pf[t] = *(const uint4*)(gp[t] + k1);
    }
#pragma unroll
    for (int s = 0; s < 2; s++) {
      const int kb = s * 8;  // word offset of this k16 half
      uint32_t bh[4][2], bl[4][2];
#pragma unroll
      for (int j = 0; j < 4; j++) {
        uint32_t off = ((wc * 32 + j * 8 + bRow) * SROW + kb + bKWord) * 4;
        ldsm_x2(bh[j], bBh + off);
        ldsm_x2(bl[j], bBl + off);
      }
#pragma unroll
      for (int i = 0; i < 4; i++) {
        uint32_t off = ((wr * 64 + i * 16 + aRowOff) * SROW + kb + aKWord) * 4;
        uint32_t ah[4], al[4];
        ldsm_x4(ah, bAh + off);
        ldsm_x4(al, bAl + off);
#pragma unroll
        for (int j = 0; j < 4; j++) {
          mma16816(acc[i][j], ah, bh[j]);
          mma16816(acc[i][j], ah, bl[j]);
          mma16816(acc[i][j], al, bh[j]);
        }
      }
    }
    __syncthreads();
  }

#pragma unroll
  for (int i = 0; i < 4; i++) {
    const int r = m0 + wr * 64 + i * 16 + lr;
#pragma unroll
    for (int j = 0; j < 4; j++) {
      const int c = n0 + wc * 32 + j * 8 + lq * 2;
      const float bx = bias[c], by = bias[c + 1];
      float2 v0 = {acc[i][j][0] + bx, acc[i][j][1] + by};
      float2 v1 = {acc[i][j][2] + bx, acc[i][j][3] + by};
      *(float2*)(out + (size_t)r * Ncols + c) = v0;
      *(float2*)(out + (size_t)(r + 8) * Ncols + c) = v1;
    }
  }
}

// ================= B_seq / C_seq =================
__global__ __launch_bounds__(256) void bc_seq_kernel(
    const float* __restrict__ xin, const float* __restrict__ binj,
    const float* __restrict__ cinj, const float* __restrict__ W_B,
    const float* __restrict__ W_C, const float* __restrict__ W_bi,
    const float* __restrict__ W_ci, float* __restrict__ Bseq,
    float* __restrict__ Cseq) {
  __shared__ float sx[DMODEL], sb[DMODEL], sc[DMODEL];
  const int l = blockIdx.x;
  for (int i = threadIdx.x; i < DMODEL; i += 256) {
    sx[i] = xin[(size_t)l * DMODEL + i];
    sb[i] = binj[(size_t)l * DMODEL + i];
    sc[i] = cinj[(size_t)l * DMODEL + i];
  }
  __syncthreads();
  const int n = threadIdx.x >> 3;
  const int part = threadIdx.x & 7;
  float s1 = 0.f, s2 = 0.f, s3 = 0.f, s4 = 0.f;
  const float* wb = W_B + (size_t)n * DMODEL;
  const float* wc = W_C + (size_t)n * DMODEL;
  const float* wbi = W_bi + (size_t)n * DMODEL;
  const float* wci = W_ci + (size_t)n * DMODEL;
#pragma unroll 8
  for (int i = 0; i < 128; i++) {
    int k = part + i * 8;
    float xv = sx[k], bv = sb[k], cv = sc[k];
    s1 = fmaf(xv, wb[k], s1);
    s2 = fmaf(bv, wbi[k], s2);
    s3 = fmaf(xv, wc[k], s3);
    s4 = fmaf(cv, wci[k], s4);
  }
#pragma unroll
  for (int off = 4; off; off >>= 1) {
    s1 += __shfl_down_sync(0xffffffffu, s1, off, 8);
    s2 += __shfl_down_sync(0xffffffffu, s2, off, 8);
    s3 += __shfl_down_sync(0xffffffffu, s3, off, 8);
    s4 += __shfl_down_sync(0xffffffffu, s4, off, 8);
  }
  if (part == 0) {
    Bseq[(size_t)l * NSTATE + n] = s1 * (1.f + tanhf(s2));
    Cseq[(size_t)l * NSTATE + n] = s3 * (1.f + tanhf(s4));
  }
}

// ================= fused exact tree scan (bank-conflict-free) =============
// phys(t) = t + t/32 breaks power-of-2 stride <-> bank aliasing.
#define SCAN_COLS 8
#define SCAN_PITCH 2113  // 2048 + 64 pad + 1 (odd -> decorrelate columns)
#define SCAN_THREADS 512
__device__ __forceinline__ int sphys(int t) { return t + (t >> 5); }

__global__ __launch_bounds__(SCAN_THREADS, 1) void fused_scan_kernel(
    const float* __restrict__ log_A, const float* __restrict__ delta,
    const float* __restrict__ Bseq, const float* __restrict__ Cseq,
    float* __restrict__ y) {
  extern __shared__ float smem[];
  float* sa = smem;
  float* sb = smem + SCAN_COLS * SCAN_PITCH;
  __shared__ float sS[8], sInv[8];
  __shared__ int sOk[8];

  const int tid = threadIdx.x;
  const int d = blockIdx.x >> 2;
  const int n0 = (blockIdx.x & 3) * 8;

  if (tid < 8) {
    float s = expf(log_A[d * NSTATE + n0 + tid]);
    sS[tid] = s;
    sInv[tid] = 1.f / s;
    sOk[tid] = fabsf(s - (float)(n0 + tid + 1)) < 1e-3f ? 1 : 0;
  }
  __syncthreads();
  const bool fast = sOk[0] && sOk[1] && sOk[2] && sOk[3] && sOk[4] && sOk[5] &&
                    sOk[6] && sOk[7];

  for (int t = tid; t < LSEQ; t += SCAN_THREADS) {
    float dt = delta[(size_t)t * DMODEL + d];
    float4 b0 = *(const float4*)(Bseq + t * NSTATE + n0);
    float4 b1 = *(const float4*)(Bseq + t * NSTATE + n0 + 4);
    float bs[8] = {b0.x, b0.y, b0.z, b0.w, b1.x, b1.y, b1.z, b1.w};
    const int pt = sphys(t);
    if (fast) {
      float E = expf(-dt);
      float e2 = E * E, e4 = e2 * e2, e8 = e4 * e4;
      float p = (n0 == 0) ? 1.f
                : (n0 == 8) ? e8
                : (n0 == 16) ? e8 * e8 : (e8 * e8) * e8;
#pragma unroll
      for (int c = 0; c < 8; c++) {
        p *= E;  // p = E^(n0+c+1) = exp(dt*A)
        sa[c * SCAN_PITCH + pt] = p;
        sb[c * SCAN_PITCH + pt] = (1.f - p) * sInv[c] * bs[c];
      }
    } else {
#pragma unroll
      for (int c = 0; c < 8; c++) {
        float a = expf(-dt * sS[c]);
        sa[c * SCAN_PITCH + pt] = a;
        sb[c * SCAN_PITCH + pt] = (1.f - a) * sInv[c] * bs[c];
      }
    }
  }
  __syncthreads();

  for (int step = 1; step < LSEQ; step <<= 1) {
    int nit = SCAN_COLS * (LSEQ / (2 * step));
    for (int i = tid; i < nit; i += SCAN_THREADS) {
      int col = i & 7;
      int pr = i >> 3;
      int l = sphys(pr * 2 * step + step - 1);
      int r = sphys(pr * 2 * step + 2 * step - 1);
      float* pa = sa + col * SCAN_PITCH;
      float* pb = sb + col * SCAN_PITCH;
      float ar = pa[r] * pa[l];
      float br = ar * pb[l] + pb[r];
      pa[r] = ar;
      pb[r] = br;
    }
    __syncthreads();
  }
  if (tid < SCAN_COLS) {
    sa[tid * SCAN_PITCH + sphys(LSEQ - 1)] = 1.f;
    sb[tid * SCAN_PITCH + sphys(LSEQ - 1)] = 0.f;
  }
  __syncthreads();
  for (int step = LSEQ >> 1; step >= 1; step >>= 1) {
    int nit = SCAN_COLS * (LSEQ / (2 * step));
    for (int i = tid; i < nit; i += SCAN_THREADS) {
      int col = i & 7;
      int pr = i >> 3;
      int l = sphys(pr * 2 * step + step - 1);
      int r = sphys(pr * 2 * step + 2 * step - 1);
      float* pa = sa + col * SCAN_PITCH;
      float* pb = sb + col * SCAN_PITCH;
      float al = pa[l], bl = pb[l];
      float ar = pa[r], br = pb[r];
      float nb = ar * bl + br;
      pa[l] = ar;
      pa[r] = ar * al;
      pb[l] = nb;
      pb[r] = nb;
    }
    __syncthreads();
  }
  for (int t = tid; t < LSEQ; t += SCAN_THREADS) {
    float acc = 0.f;
    const int pt = sphys(t);
#pragma unroll
    for (int col = 0; col < SCAN_COLS; col++)
      acc = fmaf(sb[col * SCAN_PITCH + pt], Cseq[t * NSTATE + n0 + col], acc);
    atomicAdd(&y[(size_t)t * DMODEL + d], acc);
  }
}

// ================= u = y*z + x_in =================
__global__ __launch_bounds__(256) void u_kernel(const float* __restrict__ y,
                                                const float* __restrict__ z,
                                                const float* __restrict__ xin,
                                                float* __restrict__ u) {
  size_t i = (size_t)blockIdx.x * 256 + threadIdx.x;
  u[i] = fmaf(y[i], z[i], xin[i]);
}

// ================= LayerNorm =================
__global__ __launch_bounds__(256) void layernorm_kernel(
    const float* __restrict__ u, const float* __restrict__ g,
    const float* __restrict__ beta, float* __restrict__ o) {
  const int l = blockIdx.x;
  const float* row = u + (size_t)l * DMODEL;
  float s = 0.f, s2 = 0.f;
  for (int i = threadIdx.x; i < DMODEL; i += 256) {
    float v = row[i];
    s += v;
    s2 += v * v;
  }
#pragma unroll
  for (int off = 16; off; off >>= 1) {
    s += __shfl_xor_sync(0xffffffffu, s, off);
    s2 += __shfl_xor_sync(0xffffffffu, s2, off);
  }
  __shared__ float shs[8], shs2[8];
  const int w = threadIdx.x >> 5;
  if ((threadIdx.x & 31) == 0) { shs[w] = s; shs2[w] = s2; }
  __syncthreads();
  if (threadIdx.x < 32) {
    s = (threadIdx.x < 8) ? shs[threadIdx.x] : 0.f;
    s2 = (threadIdx.x < 8) ? shs2[threadIdx.x] : 0.f;
#pragma unroll
    for (int off = 4; off; off >>= 1) {
      s += __shfl_xor_sync(0xffffffffu, s, off);
      s2 += __shfl_xor_sync(0xffffffffu, s2, off);
    }
    if (threadIdx.x == 0) { shs[0] = s; shs2[0] = s2; }
  }
  __syncthreads();
  const float mu = shs[0] * (1.f / DMODEL);
  const float var = shs2[0] * (1.f / DMODEL) - mu * mu;
  const float rstd = rsqrtf(var + 1e-5f);
  for (int i = threadIdx.x; i < DMODEL; i += 256)
    o[(size_t)l * DMODEL + i] = (row[i] - mu) * rstd * g[i] + beta[i];
}

// ================= launch =================
extern "C" void kernel_launch(void* const* d_in, const int* in_sizes, int n_in,
                              void* d_out, int out_size) {
  const float* x         = (const float*)d_in[0];
  const float* b_inject  = (const float*)d_in[1];
  const float* c_inject  = (const float*)d_in[2];
  const float* W_in      = (const float*)d_in[3];
  const float* b_in      = (const float*)d_in[4];
  const float* log_A     = (const float*)d_in[5];
  const float* W_B       = (const float*)d_in[6];
  const float* W_C       = (const float*)d_in[7];
  const float* W_delta   = (const float*)d_in[8];
  const float* b_delta   = (const float*)d_in[9];
  const float* delta_bias= (const float*)d_in[10];
  const float* W_bi      = (const float*)d_in[11];
  const float* W_ci      = (const float*)d_in[12];
  const float* ln_g      = (const float*)d_in[13];
  const float* ln_b      = (const float*)d_in[14];
  const float* W_out     = (const float*)d_in[15];
  const float* b_out     = (const float*)d_in[16];
  const float* W_vocab   = (const float*)d_in[17];
  const float* b_vocab   = (const float*)d_in[18];
  float* out = (float*)d_out;

  void* p;
  cudaGetSymbolAddress(&p, g_xin);   float* xin   = (float*)p;
  cudaGetSymbolAddress(&p, g_z);     float* zbuf  = (float*)p;
  cudaGetSymbolAddress(&p, g_delta); float* delta = (float*)p;
  cudaGetSymbolAddress(&p, g_Bseq);  float* Bseq  = (float*)p;
  cudaGetSymbolAddress(&p, g_Cseq);  float* Cseq  = (float*)p;
  cudaGetSymbolAddress(&p, g_u);     float* ubuf  = (float*)p;
  cudaGetSymbolAddress(&p, g_ln);    float* lnbuf = (float*)p;
  cudaGetSymbolAddress(&p, g_mid);   float* mid   = (float*)p;
  cudaGetSymbolAddress(&p, g_y);     float* ybuf  = (float*)p;
  cudaGetSymbolAddress(&p, g_Whi);   __nv_bfloat16* whi = (__nv_bfloat16*)p;
  cudaGetSymbolAddress(&p, g_Wlo);   __nv_bfloat16* wlo = (__nv_bfloat16*)p;
  cudaGetSymbolAddress(&p, g_midhi); __nv_bfloat16* mhi = (__nv_bfloat16*)p;
  cudaGetSymbolAddress(&p, g_midlo); __nv_bfloat16* mlo = (__nv_bfloat16*)p;

  const int scan_smem = 2 * SCAN_COLS * SCAN_PITCH * (int)sizeof(float);
  cudaFuncSetAttribute(fused_scan_kernel,
                       cudaFuncAttributeMaxDynamicSharedMemorySize, scan_smem);

  // 1. xz = x @ W_in^T + b_in -> x_in, z
  sgemm_kernel<1><<<dim3(2 * DMODEL / 128, LSEQ / 128), 256>>>(
      x, W_in, b_in, nullptr, xin, zbuf, LSEQ, 2 * DMODEL, DMODEL);
  // 2. delta
  sgemm_kernel<2><<<dim3(DMODEL / 128, LSEQ / 128), 256>>>(
      xin, W_delta, b_delta, delta_bias, delta, nullptr, LSEQ, DMODEL, DMODEL);
  // 3. B_seq / C_seq
  bc_seq_kernel<<<LSEQ, 256>>>(xin, b_inject, c_inject, W_B, W_C, W_bi, W_ci,
                               Bseq, Cseq);
  // 4. scan -> y
  cudaMemsetAsync(ybuf, 0, (size_t)LSEQ * DMODEL * sizeof(float));
  fused_scan_kernel<<<DMODEL * 4, SCAN_THREADS, scan_smem>>>(log_A, delta,
                                                             Bseq, Cseq, ybuf);
  // 5. u = y*z + x_in
  u_kernel<<<LSEQ * DMODEL / 256, 256>>>(ybuf, zbuf, xin, ubuf);
  // 6. LayerNorm
  layernorm_kernel<<<LSEQ, 256>>>(ubuf, ln_g, ln_b, lnbuf);
  // 7. mid = ln @ W_out^T + b_out
  sgemm_kernel<0><<<dim3(DMODEL / 128, LSEQ / 128), 256>>>(
      lnbuf, W_out, b_out, nullptr, mid, nullptr, LSEQ, DMODEL, DMODEL);
  // 8. split conversions
  split_kernel<<<(LSEQ * DMODEL / 4 + 255) / 256, 256>>>(mid, mhi, mlo,
                                                         LSEQ * DMODEL / 4);
  split_kernel<<<((int)((size_t)VOCAB * DMODEL / 4) + 255) / 256, 256>>>(
      W_vocab, whi, wlo, (int)((size_t)VOCAB * DMODEL / 4));
  // 9. logits = mid @ W_vocab^T + b_vocab  (bf16x3 mma.sync + ldmatrix)
  mma_gemm_kernel<<<dim3(LSEQ / 128, VOCAB / 128), 256>>>(mhi, mlo, whi, wlo,
                                                          b_vocab, out, VOCAB);
}

// round 10
// speedup vs baseline: 2.6544x; 1.4298x over previous
#include <cuda_runtime.h>
#include <cuda_bf16.h>
#include <math.h>
#include <stdint.h>

#define LSEQ 2048
#define DMODEL 1024
#define NSTATE 32
#define VOCAB 32000

// ---------------- scratch (no allocations allowed) ----------------
__device__ float g_xin[LSEQ * DMODEL];
__device__ float g_z[LSEQ * DMODEL];
__device__ float g_delta[LSEQ * DMODEL];
__device__ float g_Bseq[LSEQ * NSTATE];
__device__ float g_Cseq[LSEQ * NSTATE];
__device__ float g_u[LSEQ * DMODEL];
__device__ float g_y[LSEQ * DMODEL];
__device__ __nv_bfloat16 g_Whi[(size_t)VOCAB * DMODEL];
__device__ __nv_bfloat16 g_Wlo[(size_t)VOCAB * DMODEL];
__device__ __nv_bfloat16 g_midhi[LSEQ * DMODEL];
__device__ __nv_bfloat16 g_midlo[LSEQ * DMODEL];
__device__ __nv_bfloat16 g_xhi[LSEQ * DMODEL];
__device__ __nv_bfloat16 g_xlo[LSEQ * DMODEL];
__device__ __nv_bfloat16 g_winhi[2 * DMODEL * DMODEL];
__device__ __nv_bfloat16 g_winlo[2 * DMODEL * DMODEL];
__device__ __nv_bfloat16 g_wdhi[DMODEL * DMODEL];
__device__ __nv_bfloat16 g_wdlo[DMODEL * DMODEL];
__device__ __nv_bfloat16 g_wohi[DMODEL * DMODEL];
__device__ __nv_bfloat16 g_wolo[DMODEL * DMODEL];
__device__ __nv_bfloat16 g_xinhi[LSEQ * DMODEL];
__device__ __nv_bfloat16 g_xinlo[LSEQ * DMODEL];
__device__ __nv_bfloat16 g_lnhi[LSEQ * DMODEL];
__device__ __nv_bfloat16 g_lnlo[LSEQ * DMODEL];

__device__ __forceinline__ uint32_t smem_u32(const void* p) {
  uint32_t a;
  asm("{ .reg .u64 t; cvta.to.shared.u64 t, %1; cvt.u32.u64 %0, t; }"
      : "=r"(a) : "l"(p));
  return a;
}
__device__ __forceinline__ void split2(float v0, float v1,
                                       __nv_bfloat162* hi, __nv_bfloat162* lo) {
  __nv_bfloat16 h0 = __float2bfloat16(v0), h1 = __float2bfloat16(v1);
  __nv_bfloat162 H; H.x = h0; H.y = h1;
  __nv_bfloat162 L;
  L.x = __float2bfloat16(v0 - __bfloat162float(h0));
  L.y = __float2bfloat16(v1 - __bfloat162float(h1));
  *hi = H;
  *lo = L;
}

// ================= bf16 hi/lo split conversion =================
__global__ __launch_bounds__(256) void split_kernel(
    const float* __restrict__ src, __nv_bfloat16* __restrict__ hi,
    __nv_bfloat16* __restrict__ lo, int n4) {
  int i = blockIdx.x * 256 + threadIdx.x;
  if (i >= n4) return;
  float4 v = ((const float4*)src)[i];
  float vv[4] = {v.x, v.y, v.z, v.w};
  union { __nv_bfloat16 b[4]; uint2 u; } H, L;
#pragma unroll
  for (int j = 0; j < 4; j++) {
    __nv_bfloat16 h = __float2bfloat16(vv[j]);
    H.b[j] = h;
    L.b[j] = __float2bfloat16(vv[j] - __bfloat162float(h));
  }
  ((uint2*)hi)[i] = H.u;
  ((uint2*)lo)[i] = L.u;
}

// ================= bf16x3 GEMM via mma.sync + ldmatrix =====
// out(MxN) = A(MxK)*B(NxK)^T + bias; A=Ahi+Alo, B=Bhi+Blo (AhBh+AhBl+AlBh).
// Block 128x128, K-chunk 32, 8 warps (2x4), warp tile 64x32. K = DMODEL.
// MODE 0: fp32 out.  MODE 1: col<D -> xin fp32 + hi/lo split; col>=D -> sigmoid out2.
// MODE 2: softplus(v+bias2) fp32.  MODE 3: hi/lo split only.
#define SROW 20

__device__ __forceinline__ void mma16816(float* c, const uint32_t* a,
                                         const uint32_t* b) {
  asm volatile(
      "mma.sync.aligned.m16n8k16.row.col.f32.bf16.bf16.f32 "
      "{%0,%1,%2,%3}, {%4,%5,%6,%7}, {%8,%9}, {%0,%1,%2,%3};"
      : "+f"(c[0]), "+f"(c[1]), "+f"(c[2]), "+f"(c[3])
      : "r"(a[0]), "r"(a[1]), "r"(a[2]), "r"(a[3]), "r"(b[0]), "r"(b[1]));
}
__device__ __forceinline__ void ldsm_x4(uint32_t* r, uint32_t addr) {
  asm volatile(
      "ldmatrix.sync.aligned.m8n8.x4.shared.b16 {%0,%1,%2,%3}, [%4];"
      : "=r"(r[0]), "=r"(r[1]), "=r"(r[2]), "=r"(r[3]) : "r"(addr));
}
__device__ __forceinline__ void ldsm_x2(uint32_t* r, uint32_t addr) {
  asm volatile(
      "ldmatrix.sync.aligned.m8n8.x2.shared.b16 {%0,%1}, [%2];"
      : "=r"(r[0]), "=r"(r[1]) : "r"(addr));
}

template <int MODE>
__global__ __launch_bounds__(256, 1) void mma_gemm_kernel(
    const __nv_bfloat16* __restrict__ Ahi, const __nv_bfloat16* __restrict__ Alo,
    const __nv_bfloat16* __restrict__ Bhi, const __nv_bfloat16* __restrict__ Blo,
    const float* __restrict__ bias, const float* __restrict__ bias2,
    float* __restrict__ out, __nv_bfloat16* __restrict__ outhi,
    __nv_bfloat16* __restrict__ outlo, float* __restrict__ out2, int Ncols) {
  __shared__ uint32_t sm[4 * 128 * SROW];
  uint32_t* sAh = sm;
  uint32_t* sAl = sm + 128 * SROW;
  uint32_t* sBh = sm + 2 * 128 * SROW;
  uint32_t* sBl = sm + 3 * 128 * SROW;
  const uint32_t sb = smem_u32(sm);
  const uint32_t bAh = sb, bAl = sb + 128 * SROW * 4,
                 bBh = sb + 2 * 128 * SROW * 4, bBl = sb + 3 * 128 * SROW * 4;

  const int tid = threadIdx.x;
  const int wid = tid >> 5, lane = tid & 31;
  const int wr = wid >> 2, wc = wid & 3;
  const int m0 = blockIdx.x * 128, n0 = blockIdx.y * 128;
  const int lr = lane >> 2, lq = lane & 3;

  float acc[4][4][4];
#pragma unroll
  for (int i = 0; i < 4; i++)
#pragma unroll
    for (int j = 0; j < 4; j++)
#pragma unroll
      for (int q = 0; q < 4; q++) acc[i][j][q] = 0.f;

  const int r0 = tid >> 2, q0 = tid & 3;
  const __nv_bfloat16* gp[8] = {
      Ahi + (size_t)(m0 + r0) * DMODEL + q0 * 8,
      Ahi + (size_t)(m0 + r0 + 64) * DMODEL + q0 * 8,
      Alo + (size_t)(m0 + r0) * DMODEL + q0 * 8,
      Alo + (size_t)(m0 + r0 + 64) * DMODEL + q0 * 8,
      Bhi + (size_t)(n0 + r0) * DMODEL + q0 * 8,
      Bhi + (size_t)(n0 + r0 + 64) * DMODEL + q0 * 8,
      Blo + (size_t)(n0 + r0) * DMODEL + q0 * 8,
      Blo + (size_t)(n0 + r0 + 64) * DMODEL + q0 * 8};
  uint32_t* sp[8] = {
      sAh + r0 * SROW + q0 * 4,        sAh + (r0 + 64) * SROW + q0 * 4,
      sAl + r0 * SROW + q0 * 4,        sAl + (r0 + 64) * SROW + q0 * 4,
      sBh + r0 * SROW + q0 * 4,        sBh + (r0 + 64) * SROW + q0 * 4,
      sBl + r0 * SROW + q0 * 4,        sBl + (r0 + 64) * SROW + q0 * 4};

  const int ag = lane >> 3, ar8 = lane & 7;
  const int aRowOff = (ag & 1) * 8 + ar8;
  const int aKWord = (ag >> 1) * 4;
  const int bg = (lane >> 3) & 1;
  const int bRow = lane & 7;
  const int bKWord = bg * 4;

  uint4 pf[8];
#pragma unroll
  for (int t = 0; t < 8; t++) pf[t] = *(const uint4*)(gp[t]);

  for (int chunk = 0; chunk < DMODEL / 32; chunk++) {
#pragma unroll
    for (int t = 0; t < 8; t++) *(uint4*)(sp[t]) = pf[t];
    __syncthreads();
    if (chunk + 1 < DMODEL / 32) {
      const int k1 = (chunk + 1) * 32;
#pragma unroll
      for (int t = 0; t < 8; t++) pf[t] = *(const uint4*)(gp[t] + k1);
    }
#pragma unroll
    for (int s = 0; s < 2; s++) {
      const int kb = s * 8;
      uint32_t bh[4][2], bl[4][2];
#pragma unroll
      for (int j = 0; j < 4; j++) {
        uint32_t off = ((wc * 32 + j * 8 + bRow) * SROW + kb + bKWord) * 4;
        ldsm_x2(bh[j], bBh + off);
        ldsm_x2(bl[j], bBl + off);
      }
#pragma unroll
      for (int i = 0; i < 4; i++) {
        uint32_t off = ((wr * 64 + i * 16 + aRowOff) * SROW + kb + aKWord) * 4;
        uint32_t ah[4], al[4];
        ldsm_x4(ah, bAh + off);
        ldsm_x4(al, bAl + off);
#pragma unroll
        for (int j = 0; j < 4; j++) {
          mma16816(acc[i][j], ah, bh[j]);
          mma16816(acc[i][j], ah, bl[j]);
          mma16816(acc[i][j], al, bh[j]);
        }
      }
    }
    __syncthreads();
  }

#pragma unroll
  for (int i = 0; i < 4; i++) {
    const int r = m0 + wr * 64 + i * 16 + lr;
#pragma unroll
    for (int j = 0; j < 4; j++) {
      const int c = n0 + wc * 32 + j * 8 + lq * 2;
      const float bx = bias[c], by = bias[c + 1];
      float v00 = acc[i][j][0] + bx, v01 = acc[i][j][1] + by;
      float v10 = acc[i][j][2] + bx, v11 = acc[i][j][3] + by;
      if (MODE == 0) {
        *(float2*)(out + (size_t)r * Ncols + c) = make_float2(v00, v01);
        *(float2*)(out + (size_t)(r + 8) * Ncols + c) = make_float2(v10, v11);
      } else if (MODE == 1) {
        if (c < DMODEL) {
          *(float2*)(out + (size_t)r * DMODEL + c) = make_float2(v00, v01);
          *(float2*)(out + (size_t)(r + 8) * DMODEL + c) = make_float2(v10, v11);
          split2(v00, v01, (__nv_bfloat162*)(outhi + (size_t)r * DMODEL + c),
                 (__nv_bfloat162*)(outlo + (size_t)r * DMODEL + c));
          split2(v10, v11, (__nv_bfloat162*)(outhi + (size_t)(r + 8) * DMODEL + c),
                 (__nv_bfloat162*)(outlo + (size_t)(r + 8) * DMODEL + c));
        } else {
          const int cz = c - DMODEL;
          float2 s0 = make_float2(1.f / (1.f + expf(-v00)),
                                  1.f / (1.f + expf(-v01)));
          float2 s1 = make_float2(1.f / (1.f + expf(-v10)),
                                  1.f / (1.f + expf(-v11)));
          *(float2*)(out2 + (size_t)r * DMODEL + cz) = s0;
          *(float2*)(out2 + (size_t)(r + 8) * DMODEL + cz) = s1;
        }
      } else if (MODE == 2) {
        v00 += bias2[c];     v01 += bias2[c + 1];
        v10 += bias2[c];     v11 += bias2[c + 1];
        v00 = (v00 > 20.f) ? v00 : log1pf(expf(v00));
        v01 = (v01 > 20.f) ? v01 : log1pf(expf(v01));
        v10 = (v10 > 20.f) ? v10 : log1pf(expf(v10));
        v11 = (v11 > 20.f) ? v11 : log1pf(expf(v11));
        *(float2*)(out + (size_t)r * Ncols + c) = make_float2(v00, v01);
        *(float2*)(out + (size_t)(r + 8) * Ncols + c) = make_float2(v10, v11);
      } else {  // MODE 3: split only
        split2(v00, v01, (__nv_bfloat162*)(outhi + (size_t)r * DMODEL + c),
               (__nv_bfloat162*)(outlo + (size_t)r * DMODEL + c));
        split2(v10, v11, (__nv_bfloat162*)(outhi + (size_t)(r + 8) * DMODEL + c),
               (__nv_bfloat162*)(outlo + (size_t)(r + 8) * DMODEL + c));
      }
    }
  }
}

// ================= B_seq / C_seq =================
__global__ __launch_bounds__(256) void bc_seq_kernel(
    const float* __restrict__ xin, const float* __restrict__ binj,
    const float* __restrict__ cinj, const float* __restrict__ W_B,
    const float* __restrict__ W_C, const float* __restrict__ W_bi,
    const float* __restrict__ W_ci, float* __restrict__ Bseq,
    float* __restrict__ Cseq) {
  __shared__ float sx[DMODEL], sb[DMODEL], sc[DMODEL];
  const int l = blockIdx.x;
  for (int i = threadIdx.x; i < DMODEL; i += 256) {
    sx[i] = xin[(size_t)l * DMODEL + i];
    sb[i] = binj[(size_t)l * DMODEL + i];
    sc[i] = cinj[(size_t)l * DMODEL + i];
  }
  __syncthreads();
  const int n = threadIdx.x >> 3;
  const int part = threadIdx.x & 7;
  float s1 = 0.f, s2 = 0.f, s3 = 0.f, s4 = 0.f;
  const float* wb = W_B + (size_t)n * DMODEL;
  const float* wc = W_C + (size_t)n * DMODEL;
  const float* wbi = W_bi + (size_t)n * DMODEL;
  const float* wci = W_ci + (size_t)n * DMODEL;
#pragma unroll 8
  for (int i = 0; i < 128; i++) {
    int k = part + i * 8;
    float xv = sx[k], bv = sb[k], cv = sc[k];
    s1 = fmaf(xv, wb[k], s1);
    s2 = fmaf(bv, wbi[k], s2);
    s3 = fmaf(xv, wc[k], s3);
    s4 = fmaf(cv, wci[k], s4);
  }
#pragma unroll
  for (int off = 4; off; off >>= 1) {
    s1 += __shfl_down_sync(0xffffffffu, s1, off, 8);
    s2 += __shfl_down_sync(0xffffffffu, s2, off, 8);
    s3 += __shfl_down_sync(0xffffffffu, s3, off, 8);
    s4 += __shfl_down_sync(0xffffffffu, s4, off, 8);
  }
  if (part == 0) {
    Bseq[(size_t)l * NSTATE + n] = s1 * (1.f + tanhf(s2));
    Cseq[(size_t)l * NSTATE + n] = s3 * (1.f + tanhf(s4));
  }
}

// ================= register-resident exact tree scan =================
// Block = (d, 8 n's). Thread = (seg 0..63, col 0..7); 32 (a,b) in registers.
// Local upsweep (steps 1..16) in regs; middle tree (steps 32..1024) over 64
// segment summaries in smem; local downsweep (16..1) in regs. Arithmetic is
// identical to the reference Blelloch tree.
__global__ __launch_bounds__(512, 1) void fused_scan_kernel(
    const float* __restrict__ log_A, const float* __restrict__ delta,
    const float* __restrict__ Bseq, const float* __restrict__ Cseq,
    float* __restrict__ y) {
  __shared__ float smA[8][65], smB[8][65];
  const int tid = threadIdx.x;
  const int d = blockIdx.x >> 2;
  const int n0 = (blockIdx.x & 3) * 8;
  const int col = tid & 7, seg = tid >> 3;
  const int n = n0 + col;
  const int T0 = seg * 32;

  const float S = expf(log_A[d * NSTATE + n]);
  const float invS = 1.f / S;
  const int m = n + 1;
  const bool fast = __syncthreads_and(fabsf(S - (float)m) < 1e-3f);

  float a[32], b[32];
  if (fast) {
    // exp shared across the 8 cols of this segment via shuffles
    float e[4];
#pragma unroll
    for (int i = 0; i < 4; i++) {
      float dt = delta[(size_t)(T0 + col * 4 + i) * DMODEL + d];
      e[i] = expf(-dt);
    }
    const int gb = (tid & 31) & ~7;
#pragma unroll
    for (int j = 0; j < 32; j++) {
      float E = __shfl_sync(0xffffffffu, e[j & 3], gb + (j >> 2), 32);
      float p2 = E * E, p4 = p2 * p2, p8 = p4 * p4, p16 = p8 * p8;
      float r = 1.f;
      if (m & 1) r *= E;
      if (m & 2) r *= p2;
      if (m & 4) r *= p4;
      if (m & 8) r *= p8;
      if (m & 16) r *= p16;
      if (m & 32) r *= p16 * p16;
      a[j] = r;  // = exp(dt * A), A = -(n+1)
      b[j] = (1.f - r) * invS * Bseq[(size_t)(T0 + j) * NSTATE + n];
    }
  } else {
#pragma unroll
    for (int j = 0; j < 32; j++) {
      float dt = delta[(size_t)(T0 + j) * DMODEL + d];
      float r = expf(-dt * S);
      a[j] = r;
      b[j] = (1.f - r) * invS * Bseq[(size_t)(T0 + j) * NSTATE + n];
    }
  }

  // local upsweep: steps 1..16 (thread-local, registers)
#pragma unroll
  for (int s = 1; s <= 16; s <<= 1)
#pragma unroll
    for (int r = 2 * s - 1; r < 32; r += 2 * s) {
      const int l = r - s;
      float ar = a[r] * a[l];
      b[r] = ar * b[l] + b[r];
      a[r] = ar;
    }

  // middle tree over 64 segment summaries per column
  smA[col][seg] = a[31];
  smB[col][seg] = b[31];
  __syncthreads();
#pragma unroll
  for (int ms = 1; ms < 64; ms <<= 1) {
    int nit = 8 * (64 / (2 * ms));
    if (tid < nit) {
      int c = tid & 7, pr = tid >> 3;
      int l = pr * 2 * ms + ms - 1, r = l + ms;
      float ar = smA[c][r] * smA[c][l];
      smB[c][r] = ar * smB[c][l] + smB[c][r];
      smA[c][r] = ar;
    }
    __syncthreads();
  }
  if (tid < 8) {
    smA[tid][63] = 1.f;
    smB[tid][63] = 0.f;
  }
  __syncthreads();
#pragma unroll
  for (int ms = 32; ms >= 1; ms >>= 1) {
    int nit = 8 * (64 / (2 * ms));
    if (tid < nit) {
      int c = tid & 7, pr = tid >> 3;
      int l = pr * 2 * ms + ms - 1, r = l + ms;
      float al = smA[c][l], bl = smB[c][l];
      float ar = smA[c][r], br = smB[c][r];
      float nb = ar * bl + br;
      smA[c][l] = ar;
      smA[c][r] = ar * al;
      smB[c][l] = nb;
      smB[c][r] = nb;
    }
    __syncthreads();
  }
  a[31] = smA[col][seg];
  b[31] = smB[col][seg];

  // local downsweep: steps 16..1 (thread-local)
#pragma unroll
  for (int s = 16; s >= 1; s >>= 1)
#pragma unroll
    for (int r = 2 * s - 1; r < 32; r += 2 * s) {
      const int l = r - s;
      float al = a[l], bl = b[l];
      float ar = a[r], br = b[r];
      float nb = ar * bl + br;
      a[l] = ar;
      a[r] = ar * al;
      b[l] = nb;
      b[r] = nb;
    }

  // epilogue: y[t,d] partial = sum over 8 cols of h*C (8-lane shfl reduce)
#pragma unroll
  for (int j = 0; j < 32; j++) {
    float v = b[j] * Cseq[(size_t)(T0 + j) * NSTATE + n];
    v += __shfl_xor_sync(0xffffffffu, v, 1, 8);
    v += __shfl_xor_sync(0xffffffffu, v, 2, 8);
    v += __shfl_xor_sync(0xffffffffu, v, 4, 8);
    if (col == 0) atomicAdd(&y[(size_t)(T0 + j) * DMODEL + d], v);
  }
}

// ================= u = y*z + x_in =================
__global__ __launch_bounds__(256) void u_kernel(const float* __restrict__ y,
                                                const float* __restrict__ z,
                                                const float* __restrict__ xin,
                                                float* __restrict__ u) {
  size_t i = (size_t)blockIdx.x * 256 + threadIdx.x;
  u[i] = fmaf(y[i], z[i], xin[i]);
}

// ================= LayerNorm (emits bf16 hi/lo split) =================
__global__ __launch_bounds__(256) void layernorm_kernel(
    const float* __restrict__ u, const float* __restrict__ g,
    const float* __restrict__ beta, __nv_bfloat16* __restrict__ ohi,
    __nv_bfloat16* __restrict__ olo) {
  const int l = blockIdx.x;
  const float* row = u + (size_t)l * DMODEL;
  float s = 0.f, s2 = 0.f;
  for (int i = threadIdx.x; i < DMODEL; i += 256) {
    float v = row[i];
    s += v;
    s2 += v * v;
  }
#pragma unroll
  for (int off = 16; off; off >>= 1) {
    s += __shfl_xor_sync(0xffffffffu, s, off);
    s2 += __shfl_xor_sync(0xffffffffu, s2, off);
  }
  __shared__ float shs[8], shs2[8];
  const int w = threadIdx.x >> 5;
  if ((threadIdx.x & 31) == 0) { shs[w] = s; shs2[w] = s2; }
  __syncthreads();
  if (threadIdx.x < 32) {
    s = (threadIdx.x < 8) ? shs[threadIdx.x] : 0.f;
    s2 = (threadIdx.x < 8) ? shs2[threadIdx.x] : 0.f;
#pragma unroll
    for (int off = 4; off; off >>= 1) {
      s += __shfl_xor_sync(0xffffffffu, s, off);
      s2 += __shfl_xor_sync(0xffffffffu, s2, off);
    }
    if (threadIdx.x == 0) { shs[0] = s; shs2[0] = s2; }
  }
  __syncthreads();
  const float mu = shs[0] * (1.f / DMODEL);
  const float var = shs2[0] * (1.f / DMODEL) - mu * mu;
  const float rstd = rsqrtf(var + 1e-5f);
  for (int i = threadIdx.x * 2; i < DMODEL; i += 512) {
    float v0 = (row[i] - mu) * rstd * g[i] + beta[i];
    float v1 = (row[i + 1] - mu) * rstd * g[i + 1] + beta[i + 1];
    split2(v0, v1, (__nv_bfloat162*)(ohi + (size_t)l * DMODEL + i),
           (__nv_bfloat162*)(olo + (size_t)l * DMODEL + i));
  }
}

// ================= launch =================
extern "C" void kernel_launch(void* const* d_in, const int* in_sizes, int n_in,
                              void* d_out, int out_size) {
  const float* x         = (const float*)d_in[0];
  const float* b_inject  = (const float*)d_in[1];
  const float* c_inject  = (const float*)d_in[2];
  const float* W_in      = (const float*)d_in[3];
  const float* b_in      = (const float*)d_in[4];
  const float* log_A     = (const float*)d_in[5];
  const float* W_B       = (const float*)d_in[6];
  const float* W_C       = (const float*)d_in[7];
  const float* W_delta   = (const float*)d_in[8];
  const float* b_delta   = (const float*)d_in[9];
  const float* delta_bias= (const float*)d_in[10];
  const float* W_bi      = (const float*)d_in[11];
  const float* W_ci      = (const float*)d_in[12];
  const float* ln_g      = (const float*)d_in[13];
  const float* ln_b      = (const float*)d_in[14];
  const float* W_out     = (const float*)d_in[15];
  const float* b_out     = (const float*)d_in[16];
  const float* W_vocab   = (const float*)d_in[17];
  const float* b_vocab   = (const float*)d_in[18];
  float* out = (float*)d_out;

  void* p;
  cudaGetSymbolAddress(&p, g_xin);   float* xin   = (float*)p;
  cudaGetSymbolAddress(&p, g_z);     float* zbuf  = (float*)p;
  cudaGetSymbolAddress(&p, g_delta); float* delta = (float*)p;
  cudaGetSymbolAddress(&p, g_Bseq);  float* Bseq  = (float*)p;
  cudaGetSymbolAddress(&p, g_Cseq);  float* Cseq  = (float*)p;
  cudaGetSymbolAddress(&p, g_u);     float* ubuf  = (float*)p;
  cudaGetSymbolAddress(&p, g_y);     float* ybuf  = (float*)p;
  cudaGetSymbolAddress(&p, g_Whi);   __nv_bfloat16* whi  = (__nv_bfloat16*)p;
  cudaGetSymbolAddress(&p, g_Wlo);   __nv_bfloat16* wlo  = (__nv_bfloat16*)p;
  cudaGetSymbolAddress(&p, g_midhi); __nv_bfloat16* mhi  = (__nv_bfloat16*)p;
  cudaGetSymbolAddress(&p, g_midlo); __nv_bfloat16* mlo  = (__nv_bfloat16*)p;
  cudaGetSymbolAddress(&p, g_xhi);   __nv_bfloat16* xhi  = (__nv_bfloat16*)p;
  cudaGetSymbolAddress(&p, g_xlo);   __nv_bfloat16* xlo  = (__nv_bfloat16*)p;
  cudaGetSymbolAddress(&p, g_winhi); __nv_bfloat16* winhi= (__nv_bfloat16*)p;
  cudaGetSymbolAddress(&p, g_winlo); __nv_bfloat16* winlo= (__nv_bfloat16*)p;
  cudaGetSymbolAddress(&p, g_wdhi);  __nv_bfloat16* wdhi = (__nv_bfloat16*)p;
  cudaGetSymbolAddress(&p, g_wdlo);  __nv_bfloat16* wdlo = (__nv_bfloat16*)p;
  cudaGetSymbolAddress(&p, g_wohi);  __nv_bfloat16* wohi = (__nv_bfloat16*)p;
  cudaGetSymbolAddress(&p, g_wolo);  __nv_bfloat16* wolo = (__nv_bfloat16*)p;
  cudaGetSymbolAddress(&p, g_xinhi); __nv_bfloat16* xinhi= (__nv_bfloat16*)p;
  cudaGetSymbolAddress(&p, g_xinlo); __nv_bfloat16* xinlo= (__nv_bfloat16*)p;
  cudaGetSymbolAddress(&p, g_lnhi);  __nv_bfloat16* lnhi = (__nv_bfloat16*)p;
  cudaGetSymbolAddress(&p, g_lnlo);  __nv_bfloat16* lnlo = (__nv_bfloat16*)p;

  // 0. static splits
  split_kernel<<<(LSEQ * DMODEL / 4 + 255) / 256, 256>>>(x, xhi, xlo,
                                                         LSEQ * DMODEL / 4);
  split_kernel<<<(2 * DMODEL * DMODEL / 4 + 255) / 256, 256>>>(
      W_in, winhi, winlo, 2 * DMODEL * DMODEL / 4);
  split_kernel<<<(DMODEL * DMODEL / 4 + 255) / 256, 256>>>(
      W_delta, wdhi, wdlo, DMODEL * DMODEL / 4);
  split_kernel<<<(DMODEL * DMODEL / 4 + 255) / 256, 256>>>(
      W_out, wohi, wolo, DMODEL * DMODEL / 4);
  split_kernel<<<((int)((size_t)VOCAB * DMODEL / 4) + 255) / 256, 256>>>(
      W_vocab, whi, wlo, (int)((size_t)VOCAB * DMODEL / 4));

  // 1. xz: xin (fp32 + split) and z = sigmoid
  mma_gemm_kernel<1><<<dim3(LSEQ / 128, 2 * DMODEL / 128), 256>>>(
      xhi, xlo, winhi, winlo, b_in, nullptr, xin, xinhi, xinlo, zbuf,
      2 * DMODEL);
  // 2. delta = softplus(xin @ W_delta^T + b_delta + delta_bias)
  mma_gemm_kernel<2><<<dim3(LSEQ / 128, DMODEL / 128), 256>>>(
      xinhi, xinlo, wdhi, wdlo, b_delta, delta_bias, delta, nullptr, nullptr,
      nullptr, DMODEL);
  // 3. B_seq / C_seq
  bc_seq_kernel<<<LSEQ, 256>>>(xin, b_inject, c_inject, W_B, W_C, W_bi, W_ci,
                               Bseq, Cseq);
  // 4. scan -> y
  cudaMemsetAsync(ybuf, 0, (size_t)LSEQ * DMODEL * sizeof(float));
  fused_scan_kernel<<<DMODEL * 4, 512>>>(log_A, delta, Bseq, Cseq, ybuf);
  // 5. u = y*z + x_in
  u_kernel<<<LSEQ * DMODEL / 256, 256>>>(ybuf, zbuf, xin, ubuf);
  // 6. LayerNorm -> bf16 split
  layernorm_kernel<<<LSEQ, 256>>>(ubuf, ln_g, ln_b, lnhi, lnlo);
  // 7. mid = ln @ W_out^T + b_out  (split output only)
  mma_gemm_kernel<3><<<dim3(LSEQ / 128, DMODEL / 128), 256>>>(
      lnhi, lnlo, wohi, wolo, b_out, nullptr, nullptr, mhi, mlo, nullptr,
      DMODEL);
  // 8. logits = mid @ W_vocab^T + b_vocab
  mma_gemm_kernel<0><<<dim3(LSEQ / 128, VOCAB / 128), 256>>>(
      mhi, mlo, whi, wlo, b_vocab, nullptr, out, nullptr, nullptr, nullptr,
      VOCAB);
}

// round 11
// speedup vs baseline: 2.8858x; 1.0872x over previous
#include <cuda_runtime.h>
#include <cuda_bf16.h>
#include <math.h>
#include <stdint.h>

#define LSEQ 2048
#define DMODEL 1024
#define NSTATE 32
#define VOCAB 32000

// ---------------- scratch (no allocations allowed) ----------------
__device__ float g_xin[LSEQ * DMODEL];
__device__ float g_z[LSEQ * DMODEL];
__device__ float g_delta[LSEQ * DMODEL];
__device__ float g_Bseq[LSEQ * NSTATE];
__device__ float g_Cseq[LSEQ * NSTATE];
__device__ float g_y[LSEQ * DMODEL];
__device__ __nv_bfloat16 g_Whi[(size_t)VOCAB * DMODEL];
__device__ __nv_bfloat16 g_Wlo[(size_t)VOCAB * DMODEL];
__device__ __nv_bfloat16 g_midhi[LSEQ * DMODEL];
__device__ __nv_bfloat16 g_midlo[LSEQ * DMODEL];
__device__ __nv_bfloat16 g_xhi[LSEQ * DMODEL];
__device__ __nv_bfloat16 g_xlo[LSEQ * DMODEL];
__device__ __nv_bfloat16 g_winhi[2 * DMODEL * DMODEL];
__device__ __nv_bfloat16 g_winlo[2 * DMODEL * DMODEL];
__device__ __nv_bfloat16 g_wdhi[DMODEL * DMODEL];
__device__ __nv_bfloat16 g_wdlo[DMODEL * DMODEL];
__device__ __nv_bfloat16 g_wohi[DMODEL * DMODEL];
__device__ __nv_bfloat16 g_wolo[DMODEL * DMODEL];
__device__ __nv_bfloat16 g_xinhi[LSEQ * DMODEL];
__device__ __nv_bfloat16 g_xinlo[LSEQ * DMODEL];
__device__ __nv_bfloat16 g_lnhi[LSEQ * DMODEL];
__device__ __nv_bfloat16 g_lnlo[LSEQ * DMODEL];

__device__ __forceinline__ uint32_t smem_u32(const void* p) {
  uint32_t a;
  asm("{ .reg .u64 t; cvta.to.shared.u64 t, %1; cvt.u32.u64 %0, t; }"
      : "=r"(a) : "l"(p));
  return a;
}
__device__ __forceinline__ void split2(float v0, float v1,
                                       __nv_bfloat162* hi, __nv_bfloat162* lo) {
  __nv_bfloat16 h0 = __float2bfloat16(v0), h1 = __float2bfloat16(v1);
  __nv_bfloat162 H; H.x = h0; H.y = h1;
  __nv_bfloat162 L;
  L.x = __float2bfloat16(v0 - __bfloat162float(h0));
  L.y = __float2bfloat16(v1 - __bfloat162float(h1));
  *hi = H;
  *lo = L;
}
#define CP_ASYNC16(dst, src) \
  asm volatile("cp.async.cg.shared.global [%0], [%1], 16;" ::"r"(dst), \
               "l"(src))
#define CP_COMMIT() asm volatile("cp.async.commit_group;")
#define CP_WAIT(n) asm volatile("cp.async.wait_group %0;" ::"n"(n))

// ================= bf16 hi/lo split conversion =================
__global__ __launch_bounds__(256) void split_kernel(
    const float* __restrict__ src, __nv_bfloat16* __restrict__ hi,
    __nv_bfloat16* __restrict__ lo, int n4) {
  int i = blockIdx.x * 256 + threadIdx.x;
  if (i >= n4) return;
  float4 v = ((const float4*)src)[i];
  float vv[4] = {v.x, v.y, v.z, v.w};
  union { __nv_bfloat16 b[4]; uint2 u; } H, L;
#pragma unroll
  for (int j = 0; j < 4; j++) {
    __nv_bfloat16 h = __float2bfloat16(vv[j]);
    H.b[j] = h;
    L.b[j] = __float2bfloat16(vv[j] - __bfloat162float(h));
  }
  ((uint2*)hi)[i] = H.u;
  ((uint2*)lo)[i] = L.u;
}

// ================= bf16x3 GEMM: mma.sync + ldmatrix + cp.async x2-buffer ====
// out(MxN) = A(MxK)*B(NxK)^T + bias; A=Ahi+Alo, B=Bhi+Blo (AhBh+AhBl+AlBh).
// Block 128x128, K-chunk 32, 8 warps (2x4), warp tile 64x32. K = DMODEL.
// MODE 0: fp32 out. MODE 1: col<D -> xin fp32+split; col>=D -> sigmoid out2.
// MODE 2: softplus(v+bias2). MODE 3: hi/lo split only.
#define SROW 20
#define TILE_W (128 * SROW)            // words per tile
#define STAGE_W (4 * TILE_W)           // words per stage
#define STAGE_B (STAGE_W * 4)          // bytes per stage (40960)

__device__ __forceinline__ void mma16816(float* c, const uint32_t* a,
                                         const uint32_t* b) {
  asm volatile(
      "mma.sync.aligned.m16n8k16.row.col.f32.bf16.bf16.f32 "
      "{%0,%1,%2,%3}, {%4,%5,%6,%7}, {%8,%9}, {%0,%1,%2,%3};"
      : "+f"(c[0]), "+f"(c[1]), "+f"(c[2]), "+f"(c[3])
      : "r"(a[0]), "r"(a[1]), "r"(a[2]), "r"(a[3]), "r"(b[0]), "r"(b[1]));
}
__device__ __forceinline__ void ldsm_x4(uint32_t* r, uint32_t addr) {
  asm volatile(
      "ldmatrix.sync.aligned.m8n8.x4.shared.b16 {%0,%1,%2,%3}, [%4];"
      : "=r"(r[0]), "=r"(r[1]), "=r"(r[2]), "=r"(r[3]) : "r"(addr));
}
__device__ __forceinline__ void ldsm_x2(uint32_t* r, uint32_t addr) {
  asm volatile(
      "ldmatrix.sync.aligned.m8n8.x2.shared.b16 {%0,%1}, [%2];"
      : "=r"(r[0]), "=r"(r[1]) : "r"(addr));
}

template <int MODE>
__global__ __launch_bounds__(256, 2) void mma_gemm_kernel(
    const __nv_bfloat16* __restrict__ Ahi, const __nv_bfloat16* __restrict__ Alo,
    const __nv_bfloat16* __restrict__ Bhi, const __nv_bfloat16* __restrict__ Blo,
    const float* __restrict__ bias, const float* __restrict__ bias2,
    float* __restrict__ out, __nv_bfloat16* __restrict__ outhi,
    __nv_bfloat16* __restrict__ outlo, float* __restrict__ out2, int Ncols) {
  extern __shared__ __align__(16) uint32_t sm[];
  const uint32_t sbase = smem_u32(sm);

  const int tid = threadIdx.x;
  const int wid = tid >> 5, lane = tid & 31;
  const int wr = wid >> 2, wc = wid & 3;
  const int m0 = blockIdx.x * 128, n0 = blockIdx.y * 128;
  const int lr = lane >> 2, lq = lane & 3;

  float acc[4][4][4];
#pragma unroll
  for (int i = 0; i < 4; i++)
#pragma unroll
    for (int j = 0; j < 4; j++)
#pragma unroll
      for (int q = 0; q < 4; q++) acc[i][j][q] = 0.f;

  // copy slots: t in 0..7 -> tile t>>1 (Ah,Al,Bh,Bl), row r0 + (t&1)*64
  const int r0 = tid >> 2, q0 = tid & 3;
  const __nv_bfloat16* gp[8] = {
      Ahi + (size_t)(m0 + r0) * DMODEL + q0 * 8,
      Ahi + (size_t)(m0 + r0 + 64) * DMODEL + q0 * 8,
      Alo + (size_t)(m0 + r0) * DMODEL + q0 * 8,
      Alo + (size_t)(m0 + r0 + 64) * DMODEL + q0 * 8,
      Bhi + (size_t)(n0 + r0) * DMODEL + q0 * 8,
      Bhi + (size_t)(n0 + r0 + 64) * DMODEL + q0 * 8,
      Blo + (size_t)(n0 + r0) * DMODEL + q0 * 8,
      Blo + (size_t)(n0 + r0 + 64) * DMODEL + q0 * 8};
  uint32_t cpa[8];
#pragma unroll
  for (int t = 0; t < 8; t++)
    cpa[t] = sbase + ((t >> 1) * TILE_W + (r0 + (t & 1) * 64) * SROW + q0 * 4) * 4;

  const int ag = lane >> 3, ar8 = lane & 7;
  const int aRowOff = (ag & 1) * 8 + ar8;
  const int aKWord = (ag >> 1) * 4;
  const int bRow = lane & 7;
  const int bKWord = ((lane >> 3) & 1) * 4;

  // prologue: stage 0
#pragma unroll
  for (int t = 0; t < 8; t++) CP_ASYNC16(cpa[t], gp[t]);
  CP_COMMIT();

  for (int chunk = 0; chunk < DMODEL / 32; chunk++) {
    const int s = chunk & 1;
    if (chunk + 1 < DMODEL / 32) {
      const int k1 = (chunk + 1) * 32;
      const uint32_t so = (s ^ 1) * STAGE_B;
#pragma unroll
      for (int t = 0; t < 8; t++) CP_ASYNC16(cpa[t] + so, gp[t] + k1);
      CP_COMMIT();
      CP_WAIT(1);
    } else {
      CP_WAIT(0);
    }
    __syncthreads();

    const uint32_t bAh = sbase + s * STAGE_B;
    const uint32_t bAl = bAh + TILE_W * 4;
    const uint32_t bBh = bAh + 2 * TILE_W * 4;
    const uint32_t bBl = bAh + 3 * TILE_W * 4;
#pragma unroll
    for (int half = 0; half < 2; half++) {
      const int kb = half * 8;
      uint32_t bh[4][2], bl[4][2];
#pragma unroll
      for (int j = 0; j < 4; j++) {
        uint32_t off = ((wc * 32 + j * 8 + bRow) * SROW + kb + bKWord) * 4;
        ldsm_x2(bh[j], bBh + off);
        ldsm_x2(bl[j], bBl + off);
      }
#pragma unroll
      for (int i = 0; i < 4; i++) {
        uint32_t off = ((wr * 64 + i * 16 + aRowOff) * SROW + kb + aKWord) * 4;
        uint32_t ah[4], al[4];
        ldsm_x4(ah, bAh + off);
        ldsm_x4(al, bAl + off);
#pragma unroll
        for (int j = 0; j < 4; j++) {
          mma16816(acc[i][j], ah, bh[j]);
          mma16816(acc[i][j], ah, bl[j]);
          mma16816(acc[i][j], al, bh[j]);
        }
      }
    }
    __syncthreads();
  }

#pragma unroll
  for (int i = 0; i < 4; i++) {
    const int r = m0 + wr * 64 + i * 16 + lr;
#pragma unroll
    for (int j = 0; j < 4; j++) {
      const int c = n0 + wc * 32 + j * 8 + lq * 2;
      const float bx = bias[c], by = bias[c + 1];
      float v00 = acc[i][j][0] + bx, v01 = acc[i][j][1] + by;
      float v10 = acc[i][j][2] + bx, v11 = acc[i][j][3] + by;
      if (MODE == 0) {
        *(float2*)(out + (size_t)r * Ncols + c) = make_float2(v00, v01);
        *(float2*)(out + (size_t)(r + 8) * Ncols + c) = make_float2(v10, v11);
      } else if (MODE == 1) {
        if (c < DMODEL) {
          *(float2*)(out + (size_t)r * DMODEL + c) = make_float2(v00, v01);
          *(float2*)(out + (size_t)(r + 8) * DMODEL + c) = make_float2(v10, v11);
          split2(v00, v01, (__nv_bfloat162*)(outhi + (size_t)r * DMODEL + c),
                 (__nv_bfloat162*)(outlo + (size_t)r * DMODEL + c));
          split2(v10, v11,
                 (__nv_bfloat162*)(outhi + (size_t)(r + 8) * DMODEL + c),
                 (__nv_bfloat162*)(outlo + (size_t)(r + 8) * DMODEL + c));
        } else {
          const int cz = c - DMODEL;
          *(float2*)(out2 + (size_t)r * DMODEL + cz) =
              make_float2(1.f / (1.f + expf(-v00)), 1.f / (1.f + expf(-v01)));
          *(float2*)(out2 + (size_t)(r + 8) * DMODEL + cz) =
              make_float2(1.f / (1.f + expf(-v10)), 1.f / (1.f + expf(-v11)));
        }
      } else if (MODE == 2) {
        v00 += bias2[c];     v01 += bias2[c + 1];
        v10 += bias2[c];     v11 += bias2[c + 1];
        v00 = (v00 > 20.f) ? v00 : log1pf(expf(v00));
        v01 = (v01 > 20.f) ? v01 : log1pf(expf(v01));
        v10 = (v10 > 20.f) ? v10 : log1pf(expf(v10));
        v11 = (v11 > 20.f) ? v11 : log1pf(expf(v11));
        *(float2*)(out + (size_t)r * Ncols + c) = make_float2(v00, v01);
        *(float2*)(out + (size_t)(r + 8) * Ncols + c) = make_float2(v10, v11);
      } else {
        split2(v00, v01, (__nv_bfloat162*)(outhi + (size_t)r * DMODEL + c),
               (__nv_bfloat162*)(outlo + (size_t)r * DMODEL + c));
        split2(v10, v11, (__nv_bfloat162*)(outhi + (size_t)(r + 8) * DMODEL + c),
               (__nv_bfloat162*)(outlo + (size_t)(r + 8) * DMODEL + c));
      }
    }
  }
}

// ================= B_seq / C_seq =================
__global__ __launch_bounds__(256) void bc_seq_kernel(
    const float* __restrict__ xin, const float* __restrict__ binj,
    const float* __restrict__ cinj, const float* __restrict__ W_B,
    const float* __restrict__ W_C, const float* __restrict__ W_bi,
    const float* __restrict__ W_ci, float* __restrict__ Bseq,
    float* __restrict__ Cseq) {
  __shared__ float sx[DMODEL], sb[DMODEL], sc[DMODEL];
  const int l = blockIdx.x;
  for (int i = threadIdx.x; i < DMODEL; i += 256) {
    sx[i] = xin[(size_t)l * DMODEL + i];
    sb[i] = binj[(size_t)l * DMODEL + i];
    sc[i] = cinj[(size_t)l * DMODEL + i];
  }
  __syncthreads();
  const int n = threadIdx.x >> 3;
  const int part = threadIdx.x & 7;
  float s1 = 0.f, s2 = 0.f, s3 = 0.f, s4 = 0.f;
  const float* wb = W_B + (size_t)n * DMODEL;
  const float* wc = W_C + (size_t)n * DMODEL;
  const float* wbi = W_bi + (size_t)n * DMODEL;
  const float* wci = W_ci + (size_t)n * DMODEL;
#pragma unroll 8
  for (int i = 0; i < 128; i++) {
    int k = part + i * 8;
    float xv = sx[k], bv = sb[k], cv = sc[k];
    s1 = fmaf(xv, wb[k], s1);
    s2 = fmaf(bv, wbi[k], s2);
    s3 = fmaf(xv, wc[k], s3);
    s4 = fmaf(cv, wci[k], s4);
  }
#pragma unroll
  for (int off = 4; off; off >>= 1) {
    s1 += __shfl_down_sync(0xffffffffu, s1, off, 8);
    s2 += __shfl_down_sync(0xffffffffu, s2, off, 8);
    s3 += __shfl_down_sync(0xffffffffu, s3, off, 8);
    s4 += __shfl_down_sync(0xffffffffu, s4, off, 8);
  }
  if (part == 0) {
    Bseq[(size_t)l * NSTATE + n] = s1 * (1.f + tanhf(s2));
    Cseq[(size_t)l * NSTATE + n] = s3 * (1.f + tanhf(s4));
  }
}

// ================= register-resident exact tree scan =================
__global__ __launch_bounds__(512, 1) void fused_scan_kernel(
    const float* __restrict__ log_A, const float* __restrict__ delta,
    const float* __restrict__ Bseq, const float* __restrict__ Cseq,
    float* __restrict__ y) {
  __shared__ float smA[8][65], smB[8][65];
  const int tid = threadIdx.x;
  const int d = blockIdx.x >> 2;
  const int n0 = (blockIdx.x & 3) * 8;
  const int col = tid & 7, seg = tid >> 3;
  const int n = n0 + col;
  const int T0 = seg * 32;

  const float S = expf(log_A[d * NSTATE + n]);
  const float invS = 1.f / S;
  const int m = n + 1;
  const bool fast = __syncthreads_and(fabsf(S - (float)m) < 1e-3f);

  float a[32], b[32];
  if (fast) {
    float e[4];
#pragma unroll
    for (int i = 0; i < 4; i++) {
      float dt = delta[(size_t)(T0 + col * 4 + i) * DMODEL + d];
      e[i] = expf(-dt);
    }
    const int gb = (tid & 31) & ~7;
#pragma unroll
    for (int j = 0; j < 32; j++) {
      float E = __shfl_sync(0xffffffffu, e[j & 3], gb + (j >> 2), 32);
      float p2 = E * E, p4 = p2 * p2, p8 = p4 * p4, p16 = p8 * p8;
      float r = 1.f;
      if (m & 1) r *= E;
      if (m & 2) r *= p2;
      if (m & 4) r *= p4;
      if (m & 8) r *= p8;
      if (m & 16) r *= p16;
      if (m & 32) r *= p16 * p16;
      a[j] = r;
      b[j] = (1.f - r) * invS * Bseq[(size_t)(T0 + j) * NSTATE + n];
    }
  } else {
#pragma unroll
    for (int j = 0; j < 32; j++) {
      float dt = delta[(size_t)(T0 + j) * DMODEL + d];
      float r = expf(-dt * S);
      a[j] = r;
      b[j] = (1.f - r) * invS * Bseq[(size_t)(T0 + j) * NSTATE + n];
    }
  }

#pragma unroll
  for (int s = 1; s <= 16; s <<= 1)
#pragma unroll
    for (int r = 2 * s - 1; r < 32; r += 2 * s) {
      const int l = r - s;
      float ar = a[r] * a[l];
      b[r] = ar * b[l] + b[r];
      a[r] = ar;
    }

  smA[col][seg] = a[31];
  smB[col][seg] = b[31];
  __syncthreads();
#pragma unroll
  for (int ms = 1; ms < 64; ms <<= 1) {
    int nit = 8 * (64 / (2 * ms));
    if (tid < nit) {
      int c = tid & 7, pr = tid >> 3;
      int l = pr * 2 * ms + ms - 1, r = l + ms;
      float ar = smA[c][r] * smA[c][l];
      smB[c][r] = ar * smB[c][l] + smB[c][r];
      smA[c][r] = ar;
    }
    __syncthreads();
  }
  if (tid < 8) {
    smA[tid][63] = 1.f;
    smB[tid][63] = 0.f;
  }
  __syncthreads();
#pragma unroll
  for (int ms = 32; ms >= 1; ms >>= 1) {
    int nit = 8 * (64 / (2 * ms));
    if (tid < nit) {
      int c = tid & 7, pr = tid >> 3;
      int l = pr * 2 * ms + ms - 1, r = l + ms;
      float al = smA[c][l], bl = smB[c][l];
      float ar = smA[c][r], br = smB[c][r];
      float nb = ar * bl + br;
      smA[c][l] = ar;
      smA[c][r] = ar * al;
      smB[c][l] = nb;
      smB[c][r] = nb;
    }
    __syncthreads();
  }
  a[31] = smA[col][seg];
  b[31] = smB[col][seg];

#pragma unroll
  for (int s = 16; s >= 1; s >>= 1)
#pragma unroll
    for (int r = 2 * s - 1; r < 32; r += 2 * s) {
      const int l = r - s;
      float al = a[l], bl = b[l];
      float ar = a[r], br = b[r];
      float nb = ar * bl + br;
      a[l] = ar;
      a[r] = ar * al;
      b[l] = nb;
      b[r] = nb;
    }

#pragma unroll
  for (int j = 0; j < 32; j++) {
    float v = b[j] * Cseq[(size_t)(T0 + j) * NSTATE + n];
    v += __shfl_xor_sync(0xffffffffu, v, 1, 8);
    v += __shfl_xor_sync(0xffffffffu, v, 2, 8);
    v += __shfl_xor_sync(0xffffffffu, v, 4, 8);
    if (col == 0) atomicAdd(&y[(size_t)(T0 + j) * DMODEL + d], v);
  }
}

// ================= fused u + LayerNorm (emits bf16 hi/lo) =================
__global__ __launch_bounds__(256) void layernorm_kernel(
    const float* __restrict__ y, const float* __restrict__ z,
    const float* __restrict__ xin, const float* __restrict__ g,
    const float* __restrict__ beta, __nv_bfloat16* __restrict__ ohi,
    __nv_bfloat16* __restrict__ olo) {
  const int l = blockIdx.x;
  const size_t base = (size_t)l * DMODEL;
  float uv[4];
  float s = 0.f, s2 = 0.f;
#pragma unroll
  for (int k = 0; k < 2; k++) {
    int i = threadIdx.x * 2 + k * 512;
    float2 yy = *(const float2*)(y + base + i);
    float2 zz = *(const float2*)(z + base + i);
    float2 xx = *(const float2*)(xin + base + i);
    float u0 = fmaf(yy.x, zz.x, xx.x);
    float u1 = fmaf(yy.y, zz.y, xx.y);
    uv[k * 2] = u0;
    uv[k * 2 + 1] = u1;
    s += u0 + u1;
    s2 += u0 * u0 + u1 * u1;
  }
#pragma unroll
  for (int off = 16; off; off >>= 1) {
    s += __shfl_xor_sync(0xffffffffu, s, off);
    s2 += __shfl_xor_sync(0xffffffffu, s2, off);
  }
  __shared__ float shs[8], shs2[8];
  const int w = threadIdx.x >> 5;
  if ((threadIdx.x & 31) == 0) { shs[w] = s; shs2[w] = s2; }
  __syncthreads();
  if (threadIdx.x < 32) {
    s = (threadIdx.x < 8) ? shs[threadIdx.x] : 0.f;
    s2 = (threadIdx.x < 8) ? shs2[threadIdx.x] : 0.f;
#pragma unroll
    for (int off = 4; off; off >>= 1) {
      s += __shfl_xor_sync(0xffffffffu, s, off);
      s2 += __shfl_xor_sync(0xffffffffu, s2, off);
    }
    if (threadIdx.x == 0) { shs[0] = s; shs2[0] = s2; }
  }
  __syncthreads();
  const float mu = shs[0] * (1.f / DMODEL);
  const float var = shs2[0] * (1.f / DMODEL) - mu * mu;
  const float rstd = rsqrtf(var + 1e-5f);
#pragma unroll
  for (int k = 0; k < 2; k++) {
    int i = threadIdx.x * 2 + k * 512;
    float v0 = (uv[k * 2] - mu) * rstd * g[i] + beta[i];
    float v1 = (uv[k * 2 + 1] - mu) * rstd * g[i + 1] + beta[i + 1];
    split2(v0, v1, (__nv_bfloat162*)(ohi + base + i),
           (__nv_bfloat162*)(olo + base + i));
  }
}

// ================= launch =================
extern "C" void kernel_launch(void* const* d_in, const int* in_sizes, int n_in,
                              void* d_out, int out_size) {
  const float* x         = (const float*)d_in[0];
  const float* b_inject  = (const float*)d_in[1];
  const float* c_inject  = (const float*)d_in[2];
  const float* W_in      = (const float*)d_in[3];
  const float* b_in      = (const float*)d_in[4];
  const float* log_A     = (const float*)d_in[5];
  const float* W_B       = (const float*)d_in[6];
  const float* W_C       = (const float*)d_in[7];
  const float* W_delta   = (const float*)d_in[8];
  const float* b_delta   = (const float*)d_in[9];
  const float* delta_bias= (const float*)d_in[10];
  const float* W_bi      = (const float*)d_in[11];
  const float* W_ci      = (const float*)d_in[12];
  const float* ln_g      = (const float*)d_in[13];
  const float* ln_b      = (const float*)d_in[14];
  const float* W_out     = (const float*)d_in[15];
  const float* b_out     = (const float*)d_in[16];
  const float* W_vocab   = (const float*)d_in[17];
  const float* b_vocab   = (const float*)d_in[18];
  float* out = (float*)d_out;

  void* p;
  cudaGetSymbolAddress(&p, g_xin);   float* xin   = (float*)p;
  cudaGetSymbolAddress(&p, g_z);     float* zbuf  = (float*)p;
  cudaGetSymbolAddress(&p, g_delta); float* delta = (float*)p;
  cudaGetSymbolAddress(&p, g_Bseq);  float* Bseq  = (float*)p;
  cudaGetSymbolAddress(&p, g_Cseq);  float* Cseq  = (float*)p;
  cudaGetSymbolAddress(&p, g_y);     float* ybuf  = (float*)p;
  cudaGetSymbolAddress(&p, g_Whi);   __nv_bfloat16* whi  = (__nv_bfloat16*)p;
  cudaGetSymbolAddress(&p, g_Wlo);   __nv_bfloat16* wlo  = (__nv_bfloat16*)p;
  cudaGetSymbolAddress(&p, g_midhi); __nv_bfloat16* mhi  = (__nv_bfloat16*)p;
  cudaGetSymbolAddress(&p, g_midlo); __nv_bfloat16* mlo  = (__nv_bfloat16*)p;
  cudaGetSymbolAddress(&p, g_xhi);   __nv_bfloat16* xhi  = (__nv_bfloat16*)p;
  cudaGetSymbolAddress(&p, g_xlo);   __nv_bfloat16* xlo  = (__nv_bfloat16*)p;
  cudaGetSymbolAddress(&p, g_winhi); __nv_bfloat16* winhi= (__nv_bfloat16*)p;
  cudaGetSymbolAddress(&p, g_winlo); __nv_bfloat16* winlo= (__nv_bfloat16*)p;
  cudaGetSymbolAddress(&p, g_wdhi);  __nv_bfloat16* wdhi = (__nv_bfloat16*)p;
  cudaGetSymbolAddress(&p, g_wdlo);  __nv_bfloat16* wdlo = (__nv_bfloat16*)p;
  cudaGetSymbolAddress(&p, g_wohi);  __nv_bfloat16* wohi = (__nv_bfloat16*)p;
  cudaGetSymbolAddress(&p, g_wolo);  __nv_bfloat16* wolo = (__nv_bfloat16*)p;
  cudaGetSymbolAddress(&p, g_xinhi); __nv_bfloat16* xinhi= (__nv_bfloat16*)p;
  cudaGetSymbolAddress(&p, g_xinlo); __nv_bfloat16* xinlo= (__nv_bfloat16*)p;
  cudaGetSymbolAddress(&p, g_lnhi);  __nv_bfloat16* lnhi = (__nv_bfloat16*)p;
  cudaGetSymbolAddress(&p, g_lnlo);  __nv_bfloat16* lnlo = (__nv_bfloat16*)p;

  const int gemm_smem = 2 * STAGE_B;
  cudaFuncSetAttribute(mma_gemm_kernel<0>,
                       cudaFuncAttributeMaxDynamicSharedMemorySize, gemm_smem);
  cudaFuncSetAttribute(mma_gemm_kernel<1>,
                       cudaFuncAttributeMaxDynamicSharedMemorySize, gemm_smem);
  cudaFuncSetAttribute(mma_gemm_kernel<2>,
                       cudaFuncAttributeMaxDynamicSharedMemorySize, gemm_smem);
  cudaFuncSetAttribute(mma_gemm_kernel<3>,
                       cudaFuncAttributeMaxDynamicSharedMemorySize, gemm_smem);

  // 0. static splits
  split_kernel<<<(LSEQ * DMODEL / 4 + 255) / 256, 256>>>(x, xhi, xlo,
                                                         LSEQ * DMODEL / 4);
  split_kernel<<<(2 * DMODEL * DMODEL / 4 + 255) / 256, 256>>>(
      W_in, winhi, winlo, 2 * DMODEL * DMODEL / 4);
  split_kernel<<<(DMODEL * DMODEL / 4 + 255) / 256, 256>>>(
      W_delta, wdhi, wdlo, DMODEL * DMODEL / 4);
  split_kernel<<<(DMODEL * DMODEL / 4 + 255) / 256, 256>>>(
      W_out, wohi, wolo, DMODEL * DMODEL / 4);
  split_kernel<<<((int)((size_t)VOCAB * DMODEL / 4) + 255) / 256, 256>>>(
      W_vocab, whi, wlo, (int)((size_t)VOCAB * DMODEL / 4));

  // 1. xz: xin (fp32 + split) and z = sigmoid
  mma_gemm_kernel<1><<<dim3(LSEQ / 128, 2 * DMODEL / 128), 256, gemm_smem>>>(
      xhi, xlo, winhi, winlo, b_in, nullptr, xin, xinhi, xinlo, zbuf,
      2 * DMODEL);
  // 2. delta = softplus(xin @ W_delta^T + b_delta + delta_bias)
  mma_gemm_kernel<2><<<dim3(LSEQ / 128, DMODEL / 128), 256, gemm_smem>>>(
      xinhi, xinlo, wdhi, wdlo, b_delta, delta_bias, delta, nullptr, nullptr,
      nullptr, DMODEL);
  // 3. B_seq / C_seq
  bc_seq_kernel<<<LSEQ, 256>>>(xin, b_inject, c_inject, W_B, W_C, W_bi, W_ci,
                               Bseq, Cseq);
  // 4. scan -> y
  cudaMemsetAsync(ybuf, 0, (size_t)LSEQ * DMODEL * sizeof(float));
  fused_scan_kernel<<<DMODEL * 4, 512>>>(log_A, delta, Bseq, Cseq, ybuf);
  // 5+6. u = y*z + xin fused into LayerNorm -> bf16 split
  layernorm_kernel<<<LSEQ, 256>>>(ybuf, zbuf, xin, ln_g, ln_b, lnhi, lnlo);
  // 7. mid = ln @ W_out^T + b_out (split output only)
  mma_gemm_kernel<3><<<dim3(LSEQ / 128, DMODEL / 128), 256, gemm_smem>>>(
      lnhi, lnlo, wohi, wolo, b_out, nullptr, nullptr, mhi, mlo, nullptr,
      DMODEL);
  // 8. logits = mid @ W_vocab^T + b_vocab
  mma_gemm_kernel<0><<<dim3(LSEQ / 128, VOCAB / 128), 256, gemm_smem>>>(
      mhi, mlo, whi, wlo, b_vocab, nullptr, out, nullptr, nullptr, nullptr,
      VOCAB);
}

// round 13
// speedup vs baseline: 2.9180x; 1.0112x over previous
#include <cuda_runtime.h>
#include <cuda_bf16.h>
#include <math.h>
#include <stdint.h>

#define LSEQ 2048
#define DMODEL 1024
#define NSTATE 32
#define VOCAB 32000

// ---------------- scratch (no allocations allowed) ----------------
__device__ float g_xin[LSEQ * DMODEL];
__device__ float g_z[LSEQ * DMODEL];
__device__ float g_deltaT[DMODEL * LSEQ];  // transposed [d][t]
__device__ float g_Bseq[LSEQ * NSTATE];
__device__ float g_Cseq[LSEQ * NSTATE];
__device__ float g_y[LSEQ * DMODEL];
__device__ __nv_bfloat16 g_Whi[(size_t)VOCAB * DMODEL];
__device__ __nv_bfloat16 g_Wlo[(size_t)VOCAB * DMODEL];
__device__ __nv_bfloat16 g_midhi[LSEQ * DMODEL];
__device__ __nv_bfloat16 g_midlo[LSEQ * DMODEL];
__device__ __nv_bfloat16 g_xhi[LSEQ * DMODEL];
__device__ __nv_bfloat16 g_xlo[LSEQ * DMODEL];
__device__ __nv_bfloat16 g_winhi[2 * DMODEL * DMODEL];
__device__ __nv_bfloat16 g_winlo[2 * DMODEL * DMODEL];
__device__ __nv_bfloat16 g_wdhi[DMODEL * DMODEL];
__device__ __nv_bfloat16 g_wdlo[DMODEL * DMODEL];
__device__ __nv_bfloat16 g_wohi[DMODEL * DMODEL];
__device__ __nv_bfloat16 g_wolo[DMODEL * DMODEL];
__device__ __nv_bfloat16 g_xinhi[LSEQ * DMODEL];
__device__ __nv_bfloat16 g_xinlo[LSEQ * DMODEL];
__device__ __nv_bfloat16 g_lnhi[LSEQ * DMODEL];
__device__ __nv_bfloat16 g_lnlo[LSEQ * DMODEL];

__device__ __forceinline__ uint32_t smem_u32(const void* p) {
  uint32_t a;
  asm("{ .reg .u64 t; cvta.to.shared.u64 t, %1; cvt.u32.u64 %0, t; }"
      : "=r"(a) : "l"(p));
  return a;
}
__device__ __forceinline__ void split2(float v0, float v1,
                                       __nv_bfloat162* hi, __nv_bfloat162* lo) {
  __nv_bfloat16 h0 = __float2bfloat16(v0), h1 = __float2bfloat16(v1);
  __nv_bfloat162 H; H.x = h0; H.y = h1;
  __nv_bfloat162 L;
  L.x = __float2bfloat16(v0 - __bfloat162float(h0));
  L.y = __float2bfloat16(v1 - __bfloat162float(h1));
  *hi = H;
  *lo = L;
}
#define CP_ASYNC16(dst, src) \
  asm volatile("cp.async.cg.shared.global [%0], [%1], 16;" ::"r"(dst), \
               "l"(src))
#define CP_COMMIT() asm volatile("cp.async.commit_group;")
#define CP_WAIT(n) asm volatile("cp.async.wait_group %0;" ::"n"(n))

// ================= bf16 hi/lo split conversion =================
__global__ __launch_bounds__(256) void split_kernel(
    const float* __restrict__ src, __nv_bfloat16* __restrict__ hi,
    __nv_bfloat16* __restrict__ lo, int n4) {
  int i = blockIdx.x * 256 + threadIdx.x;
  if (i >= n4) return;
  float4 v = ((const float4*)src)[i];
  float vv[4] = {v.x, v.y, v.z, v.w};
  union { __nv_bfloat16 b[4]; uint2 u; } H, L;
#pragma unroll
  for (int j = 0; j < 4; j++) {
    __nv_bfloat16 h = __float2bfloat16(vv[j]);
    H.b[j] = h;
    L.b[j] = __float2bfloat16(vv[j] - __bfloat162float(h));
  }
  ((uint2*)hi)[i] = H.u;
  ((uint2*)lo)[i] = L.u;
}

// ================= bf16x3 GEMM: mma.sync + ldmatrix + cp.async x2-buffer ====
// out(MxN) = A(MxK)*B(NxK)^T + bias; A=Ahi+Alo, B=Bhi+Blo (AhBh+AhBl+AlBh).
// Block 128x128, K-chunk 32, 8 warps (2x4), warp tile 64x32. K = DMODEL.
// MODE 0: fp32 out. MODE 1: col<D -> xin fp32+split; col>=D -> sigmoid out2.
// MODE 2: softplus(v+bias2) written TRANSPOSED [col][row]. MODE 3: split only.
#define SROW 20
#define TILE_W (128 * SROW)
#define STAGE_W (4 * TILE_W)
#define STAGE_B (STAGE_W * 4)

__device__ __forceinline__ void mma16816(float* c, const uint32_t* a,
                                         const uint32_t* b) {
  asm volatile(
      "mma.sync.aligned.m16n8k16.row.col.f32.bf16.bf16.f32 "
      "{%0,%1,%2,%3}, {%4,%5,%6,%7}, {%8,%9}, {%0,%1,%2,%3};"
      : "+f"(c[0]), "+f"(c[1]), "+f"(c[2]), "+f"(c[3])
      : "r"(a[0]), "r"(a[1]), "r"(a[2]), "r"(a[3]), "r"(b[0]), "r"(b[1]));
}
__device__ __forceinline__ void ldsm_x4(uint32_t* r, uint32_t addr) {
  asm volatile(
      "ldmatrix.sync.aligned.m8n8.x4.shared.b16 {%0,%1,%2,%3}, [%4];"
      : "=r"(r[0]), "=r"(r[1]), "=r"(r[2]), "=r"(r[3]) : "r"(addr));
}
__device__ __forceinline__ void ldsm_x2(uint32_t* r, uint32_t addr) {
  asm volatile(
      "ldmatrix.sync.aligned.m8n8.x2.shared.b16 {%0,%1}, [%2];"
      : "=r"(r[0]), "=r"(r[1]) : "r"(addr));
}

template <int MODE>
__global__ __launch_bounds__(256, 2) void mma_gemm_kernel(
    const __nv_bfloat16* __restrict__ Ahi, const __nv_bfloat16* __restrict__ Alo,
    const __nv_bfloat16* __restrict__ Bhi, const __nv_bfloat16* __restrict__ Blo,
    const float* __restrict__ bias, const float* __restrict__ bias2,
    float* __restrict__ out, __nv_bfloat16* __restrict__ outhi,
    __nv_bfloat16* __restrict__ outlo, float* __restrict__ out2, int Ncols) {
  extern __shared__ __align__(16) uint32_t sm[];
  const uint32_t sbase = smem_u32(sm);

  const int tid = threadIdx.x;
  const int wid = tid >> 5, lane = tid & 31;
  const int wr = wid >> 2, wc = wid & 3;
  const int m0 = blockIdx.x * 128, n0 = blockIdx.y * 128;
  const int lr = lane >> 2, lq = lane & 3;

  float acc[4][4][4];
#pragma unroll
  for (int i = 0; i < 4; i++)
#pragma unroll
    for (int j = 0; j < 4; j++)
#pragma unroll
      for (int q = 0; q < 4; q++) acc[i][j][q] = 0.f;

  const int r0 = tid >> 2, q0 = tid & 3;
  const __nv_bfloat16* gp[8] = {
      Ahi + (size_t)(m0 + r0) * DMODEL + q0 * 8,
      Ahi + (size_t)(m0 + r0 + 64) * DMODEL + q0 * 8,
      Alo + (size_t)(m0 + r0) * DMODEL + q0 * 8,
      Alo + (size_t)(m0 + r0 + 64) * DMODEL + q0 * 8,
      Bhi + (size_t)(n0 + r0) * DMODEL + q0 * 8,
      Bhi + (size_t)(n0 + r0 + 64) * DMODEL + q0 * 8,
      Blo + (size_t)(n0 + r0) * DMODEL + q0 * 8,
      Blo + (size_t)(n0 + r0 + 64) * DMODEL + q0 * 8};
  uint32_t cpa[8];
#pragma unroll
  for (int t = 0; t < 8; t++)
    cpa[t] = sbase + ((t >> 1) * TILE_W + (r0 + (t & 1) * 64) * SROW + q0 * 4) * 4;

  const int ag = lane >> 3, ar8 = lane & 7;
  const int aRowOff = (ag & 1) * 8 + ar8;
  const int aKWord = (ag >> 1) * 4;
  const int bRow = lane & 7;
  const int bKWord = ((lane >> 3) & 1) * 4;

#pragma unroll
  for (int t = 0; t < 8; t++) CP_ASYNC16(cpa[t], gp[t]);
  CP_COMMIT();

  for (int chunk = 0; chunk < DMODEL / 32; chunk++) {
    const int s = chunk & 1;
    if (chunk + 1 < DMODEL / 32) {
      const int k1 = (chunk + 1) * 32;
      const uint32_t so = (s ^ 1) * STAGE_B;
#pragma unroll
      for (int t = 0; t < 8; t++) CP_ASYNC16(cpa[t] + so, gp[t] + k1);
      CP_COMMIT();
      CP_WAIT(1);
    } else {
      CP_WAIT(0);
    }
    __syncthreads();

    const uint32_t bAh = sbase + s * STAGE_B;
    const uint32_t bAl = bAh + TILE_W * 4;
    const uint32_t bBh = bAh + 2 * TILE_W * 4;
    const uint32_t bBl = bAh + 3 * TILE_W * 4;
#pragma unroll
    for (int half = 0; half < 2; half++) {
      const int kb = half * 8;
      uint32_t bh[4][2], bl[4][2];
#pragma unroll
      for (int j = 0; j < 4; j++) {
        uint32_t off = ((wc * 32 + j * 8 + bRow) * SROW + kb + bKWord) * 4;
        ldsm_x2(bh[j], bBh + off);
        ldsm_x2(bl[j], bBl + off);
      }
#pragma unroll
      for (int i = 0; i < 4; i++) {
        uint32_t off = ((wr * 64 + i * 16 + aRowOff) * SROW + kb + aKWord) * 4;
        uint32_t ah[4], al[4];
        ldsm_x4(ah, bAh + off);
        ldsm_x4(al, bAl + off);
        // product-major: same-acc reuse distance 4 (was 1) -> no HMMA RAW chain
#pragma unroll
        for (int j = 0; j < 4; j++) mma16816(acc[i][j], ah, bh[j]);
#pragma unroll
        for (int j = 0; j < 4; j++) mma16816(acc[i][j], ah, bl[j]);
#pragma unroll
        for (int j = 0; j < 4; j++) mma16816(acc[i][j], al, bh[j]);
      }
    }
    __syncthreads();
  }

#pragma unroll
  for (int i = 0; i < 4; i++) {
    const int r = m0 + wr * 64 + i * 16 + lr;
#pragma unroll
    for (int j = 0; j < 4; j++) {
      const int c = n0 + wc * 32 + j * 8 + lq * 2;
      const float bx = bias[c], by = bias[c + 1];
      float v00 = acc[i][j][0] + bx, v01 = acc[i][j][1] + by;
      float v10 = acc[i][j][2] + bx, v11 = acc[i][j][3] + by;
      if (MODE == 0) {
        *(float2*)(out + (size_t)r * Ncols + c) = make_float2(v00, v01);
        *(float2*)(out + (size_t)(r + 8) * Ncols + c) = make_float2(v10, v11);
      } else if (MODE == 1) {
        if (c < DMODEL) {
          *(float2*)(out + (size_t)r * DMODEL + c) = make_float2(v00, v01);
          *(float2*)(out + (size_t)(r + 8) * DMODEL + c) = make_float2(v10, v11);
          split2(v00, v01, (__nv_bfloat162*)(outhi + (size_t)r * DMODEL + c),
                 (__nv_bfloat162*)(outlo + (size_t)r * DMODEL + c));
          split2(v10, v11,
                 (__nv_bfloat162*)(outhi + (size_t)(r + 8) * DMODEL + c),
                 (__nv_bfloat162*)(outlo + (size_t)(r + 8) * DMODEL + c));
        } else {
          const int cz = c - DMODEL;
          *(float2*)(out2 + (size_t)r * DMODEL + cz) =
              make_float2(1.f / (1.f + expf(-v00)), 1.f / (1.f + expf(-v01)));
          *(float2*)(out2 + (size_t)(r + 8) * DMODEL + cz) =
              make_float2(1.f / (1.f + expf(-v10)), 1.f / (1.f + expf(-v11)));
        }
      } else if (MODE == 2) {
        v00 += bias2[c];     v01 += bias2[c + 1];
        v10 += bias2[c];     v11 += bias2[c + 1];
        v00 = (v00 > 20.f) ? v00 : log1pf(expf(v00));
        v01 = (v01 > 20.f) ? v01 : log1pf(expf(v01));
        v10 = (v10 > 20.f) ? v10 : log1pf(expf(v10));
        v11 = (v11 > 20.f) ? v11 : log1pf(expf(v11));
        // transposed [col][row] for coalesced scan reads
        out[(size_t)c * LSEQ + r] = v00;
        out[(size_t)(c + 1) * LSEQ + r] = v01;
        out[(size_t)c * LSEQ + r + 8] = v10;
        out[(size_t)(c + 1) * LSEQ + r + 8] = v11;
      } else {
        split2(v00, v01, (__nv_bfloat162*)(outhi + (size_t)r * DMODEL + c),
               (__nv_bfloat162*)(outlo + (size_t)r * DMODEL + c));
        split2(v10, v11, (__nv_bfloat162*)(outhi + (size_t)(r + 8) * DMODEL + c),
               (__nv_bfloat162*)(outlo + (size_t)(r + 8) * DMODEL + c));
      }
    }
  }
}

// ================= B_seq / C_seq =================
__global__ __launch_bounds__(256) void bc_seq_kernel(
    const float* __restrict__ xin, const float* __restrict__ binj,
    const float* __restrict__ cinj, const float* __restrict__ W_B,
    const float* __restrict__ W_C, const float* __restrict__ W_bi,
    const float* __restrict__ W_ci, float* __restrict__ Bseq,
    float* __restrict__ Cseq) {
  __shared__ float sx[DMODEL], sb[DMODEL], sc[DMODEL];
  const int l = blockIdx.x;
  for (int i = threadIdx.x; i < DMODEL; i += 256) {
    sx[i] = xin[(size_t)l * DMODEL + i];
    sb[i] = binj[(size_t)l * DMODEL + i];
    sc[i] = cinj[(size_t)l * DMODEL + i];
  }
  __syncthreads();
  const int n = threadIdx.x >> 3;
  const int part = threadIdx.x & 7;
  float s1 = 0.f, s2 = 0.f, s3 = 0.f, s4 = 0.f;
  const float* wb = W_B + (size_t)n * DMODEL;
  const float* wc = W_C + (size_t)n * DMODEL;
  const float* wbi = W_bi + (size_t)n * DMODEL;
  const float* wci = W_ci + (size_t)n * DMODEL;
#pragma unroll 8
  for (int i = 0; i < 128; i++) {
    int k = part + i * 8;
    float xv = sx[k], bv = sb[k], cv = sc[k];
    s1 = fmaf(xv, wb[k], s1);
    s2 = fmaf(bv, wbi[k], s2);
    s3 = fmaf(xv, wc[k], s3);
    s4 = fmaf(cv, wci[k], s4);
  }
#pragma unroll
  for (int off = 4; off; off >>= 1) {
    s1 += __shfl_down_sync(0xffffffffu, s1, off, 8);
    s2 += __shfl_down_sync(0xffffffffu, s2, off, 8);
    s3 += __shfl_down_sync(0xffffffffu, s3, off, 8);
    s4 += __shfl_down_sync(0xffffffffu, s4, off, 8);
  }
  if (part == 0) {
    Bseq[(size_t)l * NSTATE + n] = s1 * (1.f + tanhf(s2));
    Cseq[(size_t)l * NSTATE + n] = s3 * (1.f + tanhf(s4));
  }
}

// ================= register-resident exact tree scan (deltaT input) ========
__global__ __launch_bounds__(512, 1) void fused_scan_kernel(
    const float* __restrict__ log_A, const float* __restrict__ deltaT,
    const float* __restrict__ Bseq, const float* __restrict__ Cseq,
    float* __restrict__ y) {
  __shared__ float smA[8][65], smB[8][65];
  const int tid = threadIdx.x;
  const int d = blockIdx.x >> 2;
  const int n0 = (blockIdx.x & 3) * 8;
  const int col = tid & 7, seg = tid >> 3;
  const int n = n0 + col;
  const int T0 = seg * 32;

  const float S = expf(log_A[d * NSTATE + n]);
  const float invS = 1.f / S;
  const int m = n + 1;
  const bool fast = __syncthreads_and(fabsf(S - (float)m) < 1e-3f);

  float a[32], b[32];
  if (fast) {
    // coalesced float4 load of deltaT; exps shared across 8 cols via shfl
    float4 dt4 = *(const float4*)(deltaT + (size_t)d * LSEQ + T0 + col * 4);
    float e[4] = {expf(-dt4.x), expf(-dt4.y), expf(-dt4.z), expf(-dt4.w)};
    const int gb = (tid & 31) & ~7;
#pragma unroll
    for (int j = 0; j < 32; j++) {
      float E = __shfl_sync(0xffffffffu, e[j & 3], gb + (j >> 2), 32);
      float p2 = E * E, p4 = p2 * p2, p8 = p4 * p4, p16 = p8 * p8;
      float r = 1.f;
      if (m & 1) r *= E;
      if (m & 2) r *= p2;
      if (m & 4) r *= p4;
      if (m & 8) r *= p8;
      if (m & 16) r *= p16;
      if (m & 32) r *= p16 * p16;
      a[j] = r;
      b[j] = (1.f - r) * invS * Bseq[(size_t)(T0 + j) * NSTATE + n];
    }
  } else {
#pragma unroll
    for (int j = 0; j < 32; j++) {
      float dt = deltaT[(size_t)d * LSEQ + T0 + j];
      float r = expf(-dt * S);
      a[j] = r;
      b[j] = (1.f - r) * invS * Bseq[(size_t)(T0 + j) * NSTATE + n];
    }
  }

#pragma unroll
  for (int s = 1; s <= 16; s <<= 1)
#pragma unroll
    for (int r = 2 * s - 1; r < 32; r += 2 * s) {
      const int l = r - s;
      float ar = a[r] * a[l];
      b[r] = ar * b[l] + b[r];
      a[r] = ar;
    }

  smA[col][seg] = a[31];
  smB[col][seg] = b[31];
  __syncthreads();
#pragma unroll
  for (int ms = 1; ms < 64; ms <<= 1) {
    int nit = 8 * (64 / (2 * ms));
    if (tid < nit) {
      int c = tid & 7, pr = tid >> 3;
      int l = pr * 2 * ms + ms - 1, r = l + ms;
      float ar = smA[c][r] * smA[c][l];
      smB[c][r] = ar * smB[c][l] + smB[c][r];
      smA[c][r] = ar;
    }
    __syncthreads();
  }
  if (tid < 8) {
    smA[tid][63] = 1.f;
    smB[tid][63] = 0.f;
  }
  __syncthreads();
#pragma unroll
  for (int ms = 32; ms >= 1; ms >>= 1) {
    int nit = 8 * (64 / (2 * ms));
    if (tid < nit) {
      int c = tid & 7, pr = tid >> 3;
      int l = pr * 2 * ms + ms - 1, r = l + ms;
      float al = smA[c][l], bl = smB[c][l];
      float ar = smA[c][r], br = smB[c][r];
      float nb = ar * bl + br;
      smA[c][l] = ar;
      smA[c][r] = ar * al;
      smB[c][l] = nb;
      smB[c][r] = nb;
    }
    __syncthreads();
  }
  a[31] = smA[col][seg];
  b[31] = smB[col][seg];

#pragma unroll
  for (int s = 16; s >= 1; s >>= 1)
#pragma unroll
    for (int r = 2 * s - 1; r < 32; r += 2 * s) {
      const int l = r - s;
      float al = a[l], bl = b[l];
      float ar = a[r], br = b[r];
      float nb = ar * bl + br;
      a[l] = ar;
      a[r] = ar * al;
      b[l] = nb;
      b[r] = nb;
    }

#pragma unroll
  for (int j = 0; j < 32; j++) {
    float v = b[j] * Cseq[(size_t)(T0 + j) * NSTATE + n];
    v += __shfl_xor_sync(0xffffffffu, v, 1, 8);
    v += __shfl_xor_sync(0xffffffffu, v, 2, 8);
    v += __shfl_xor_sync(0xffffffffu, v, 4, 8);
    if (col == 0) atomicAdd(&y[(size_t)(T0 + j) * DMODEL + d], v);
  }
}

// ================= fused u + LayerNorm (emits bf16 hi/lo) =================
__global__ __launch_bounds__(256) void layernorm_kernel(
    const float* __restrict__ y, const float* __restrict__ z,
    const float* __restrict__ xin, const float* __restrict__ g,
    const float* __restrict__ beta, __nv_bfloat16* __restrict__ ohi,
    __nv_bfloat16* __restrict__ olo) {
  const int l = blockIdx.x;
  const size_t base = (size_t)l * DMODEL;
  float uv[4];
  float s = 0.f, s2 = 0.f;
#pragma unroll
  for (int k = 0; k < 2; k++) {
    int i = threadIdx.x * 2 + k * 512;
    float2 yy = *(const float2*)(y + base + i);
    float2 zz = *(const float2*)(z + base + i);
    float2 xx = *(const float2*)(xin + base + i);
    float u0 = fmaf(yy.x, zz.x, xx.x);
    float u1 = fmaf(yy.y, zz.y, xx.y);
    uv[k * 2] = u0;
    uv[k * 2 + 1] = u1;
    s += u0 + u1;
    s2 += u0 * u0 + u1 * u1;
  }
#pragma unroll
  for (int off = 16; off; off >>= 1) {
    s += __shfl_xor_sync(0xffffffffu, s, off);
    s2 += __shfl_xor_sync(0xffffffffu, s2, off);
  }
  __shared__ float shs[8], shs2[8];
  const int w = threadIdx.x >> 5;
  if ((threadIdx.x & 31) == 0) { shs[w] = s; shs2[w] = s2; }
  __syncthreads();
  if (threadIdx.x < 32) {
    s = (threadIdx.x < 8) ? shs[threadIdx.x] : 0.f;
    s2 = (threadIdx.x < 8) ? shs2[threadIdx.x] : 0.f;
#pragma unroll
    for (int off = 4; off; off >>= 1) {
      s += __shfl_xor_sync(0xffffffffu, s, off);
      s2 += __shfl_xor_sync(0xffffffffu, s2, off);
    }
    if (threadIdx.x == 0) { shs[0] = s; shs2[0] = s2; }
  }
  __syncthreads();
  const float mu = shs[0] * (1.f / DMODEL);
  const float var = shs2[0] * (1.f / DMODEL) - mu * mu;
  const float rstd = rsqrtf(var + 1e-5f);
#pragma unroll
  for (int k = 0; k < 2; k++) {
    int i = threadIdx.x * 2 + k * 512;
    float v0 = (uv[k * 2] - mu) * rstd * g[i] + beta[i];
    float v1 = (uv[k * 2 + 1] - mu) * rstd * g[i + 1] + beta[i + 1];
    split2(v0, v1, (__nv_bfloat162*)(ohi + base + i),
           (__nv_bfloat162*)(olo + base + i));
  }
}

// ================= launch =================
extern "C" void kernel_launch(void* const* d_in, const int* in_sizes, int n_in,
                              void* d_out, int out_size) {
  const float* x         = (const float*)d_in[0];
  const float* b_inject  = (const float*)d_in[1];
  const float* c_inject  = (const float*)d_in[2];
  const float* W_in      = (const float*)d_in[3];
  const float* b_in      = (const float*)d_in[4];
  const float* log_A     = (const float*)d_in[5];
  const float* W_B       = (const float*)d_in[6];
  const float* W_C       = (const float*)d_in[7];
  const float* W_delta   = (const float*)d_in[8];
  const float* b_delta   = (const float*)d_in[9];
  const float* delta_bias= (const float*)d_in[10];
  const float* W_bi      = (const float*)d_in[11];
  const float* W_ci      = (const float*)d_in[12];
  const float* ln_g      = (const float*)d_in[13];
  const float* ln_b      = (const float*)d_in[14];
  const float* W_out     = (const float*)d_in[15];
  const float* b_out     = (const float*)d_in[16];
  const float* W_vocab   = (const float*)d_in[17];
  const float* b_vocab   = (const float*)d_in[18];
  float* out = (float*)d_out;

  void* p;
  cudaGetSymbolAddress(&p, g_xin);    float* xin    = (float*)p;
  cudaGetSymbolAddress(&p, g_z);      float* zbuf   = (float*)p;
  cudaGetSymbolAddress(&p, g_deltaT); float* deltaT = (float*)p;
  cudaGetSymbolAddress(&p, g_Bseq);   float* Bseq   = (float*)p;
  cudaGetSymbolAddress(&p, g_Cseq);   float* Cseq   = (float*)p;
  cudaGetSymbolAddress(&p, g_y);      float* ybuf   = (float*)p;
  cudaGetSymbolAddress(&p, g_Whi);    __nv_bfloat16* whi  = (__nv_bfloat16*)p;
  cudaGetSymbolAddress(&p, g_Wlo);    __nv_bfloat16* wlo  = (__nv_bfloat16*)p;
  cudaGetSymbolAddress(&p, g_midhi);  __nv_bfloat16* mhi  = (__nv_bfloat16*)p;
  cudaGetSymbolAddress(&p, g_midlo);  __nv_bfloat16* mlo  = (__nv_bfloat16*)p;
  cudaGetSymbolAddress(&p, g_xhi);    __nv_bfloat16* xhi  = (__nv_bfloat16*)p;
  cudaGetSymbolAddress(&p, g_xlo);    __nv_bfloat16* xlo  = (__nv_bfloat16*)p;
  cudaGetSymbolAddress(&p, g_winhi);  __nv_bfloat16* winhi= (__nv_bfloat16*)p;
  cudaGetSymbolAddress(&p, g_winlo);  __nv_bfloat16* winlo= (__nv_bfloat16*)p;
  cudaGetSymbolAddress(&p, g_wdhi);   __nv_bfloat16* wdhi = (__nv_bfloat16*)p;
  cudaGetSymbolAddress(&p, g_wdlo);   __nv_bfloat16* wdlo = (__nv_bfloat16*)p;
  cudaGetSymbolAddress(&p, g_wohi);   __nv_bfloat16* wohi = (__nv_bfloat16*)p;
  cudaGetSymbolAddress(&p, g_wolo);   __nv_bfloat16* wolo = (__nv_bfloat16*)p;
  cudaGetSymbolAddress(&p, g_xinhi);  __nv_bfloat16* xinhi= (__nv_bfloat16*)p;
  cudaGetSymbolAddress(&p, g_xinlo);  __nv_bfloat16* xinlo= (__nv_bfloat16*)p;
  cudaGetSymbolAddress(&p, g_lnhi);   __nv_bfloat16* lnhi = (__nv_bfloat16*)p;
  cudaGetSymbolAddress(&p, g_lnlo);   __nv_bfloat16* lnlo = (__nv_bfloat16*)p;

  const int gemm_smem = 2 * STAGE_B;
  cudaFuncSetAttribute(mma_gemm_kernel<0>,
                       cudaFuncAttributeMaxDynamicSharedMemorySize, gemm_smem);
  cudaFuncSetAttribute(mma_gemm_kernel<1>,
                       cudaFuncAttributeMaxDynamicSharedMemorySize, gemm_smem);
  cudaFuncSetAttribute(mma_gemm_kernel<2>,
                       cudaFuncAttributeMaxDynamicSharedMemorySize, gemm_smem);
  cudaFuncSetAttribute(mma_gemm_kernel<3>,
                       cudaFuncAttributeMaxDynamicSharedMemorySize, gemm_smem);

  // 0. static splits
  split_kernel<<<(LSEQ * DMODEL / 4 + 255) / 256, 256>>>(x, xhi, xlo,
                                                         LSEQ * DMODEL / 4);
  split_kernel<<<(2 * DMODEL * DMODEL / 4 + 255) / 256, 256>>>(
      W_in, winhi, winlo, 2 * DMODEL * DMODEL / 4);
  split_kernel<<<(DMODEL * DMODEL / 4 + 255) / 256, 256>>>(
      W_delta, wdhi, wdlo, DMODEL * DMODEL / 4);
  split_kernel<<<(DMODEL * DMODEL / 4 + 255) / 256, 256>>>(
      W_out, wohi, wolo, DMODEL * DMODEL / 4);
  split_kernel<<<((int)((size_t)VOCAB * DMODEL / 4) + 255) / 256, 256>>>(
      W_vocab, whi, wlo, (int)((size_t)VOCAB * DMODEL / 4));

  // 1. xz: xin (fp32 + split) and z = sigmoid
  mma_gemm_kernel<1><<<dim3(LSEQ / 128, 2 * DMODEL / 128), 256, gemm_smem>>>(
      xhi, xlo, winhi, winlo, b_in, nullptr, xin, xinhi, xinlo, zbuf,
      2 * DMODEL);
  // 2. deltaT = softplus(...)^T
  mma_gemm_kernel<2><<<dim3(LSEQ / 128, DMODEL / 128), 256, gemm_smem>>>(
      xinhi, xinlo, wdhi, wdlo, b_delta, delta_bias, deltaT, nullptr, nullptr,
      nullptr, DMODEL);
  // 3. B_seq / C_seq
  bc_seq_kernel<<<LSEQ, 256>>>(xin, b_inject, c_inject, W_B, W_C, W_bi, W_ci,
                               Bseq, Cseq);
  // 4. scan -> y
  cudaMemsetAsync(ybuf, 0, (size_t)LSEQ * DMODEL * sizeof(float));
  fused_scan_kernel<<<DMODEL * 4, 512>>>(log_A, deltaT, Bseq, Cseq, ybuf);
  // 5+6. u fused into LayerNorm -> bf16 split
  layernorm_kernel<<<LSEQ, 256>>>(ybuf, zbuf, xin, ln_g, ln_b, lnhi, lnlo);
  // 7. mid = ln @ W_out^T + b_out (split output only)
  mma_gemm_kernel<3><<<dim3(LSEQ / 128, DMODEL / 128), 256, gemm_smem>>>(
      lnhi, lnlo, wohi, wolo, b_out, nullptr, nullptr, mhi, mlo, nullptr,
      DMODEL);
  // 8. logits = mid @ W_vocab^T + b_vocab
  mma_gemm_kernel<0><<<dim3(LSEQ / 128, VOCAB / 128), 256, gemm_smem>>>(
      mhi, mlo, whi, wlo, b_vocab, nullptr, out, nullptr, nullptr, nullptr,
      VOCAB);
}

// round 16
// speedup vs baseline: 3.7041x; 1.2694x over previous
#include <cuda_runtime.h>
#include <cuda_bf16.h>
#include <cuda_fp16.h>
#include <math.h>
#include <stdint.h>

#define LSEQ 2048
#define DMODEL 1024
#define NSTATE 32
#define VOCAB 32000

// ---------------- scratch (no allocations allowed) ----------------
__device__ float g_xin[LSEQ * DMODEL];
__device__ float g_z[LSEQ * DMODEL];
__device__ float g_deltaT[DMODEL * LSEQ];
__device__ float g_Bseq[LSEQ * NSTATE];
__device__ float g_Cseq[LSEQ * NSTATE];
__device__ float g_y[LSEQ * DMODEL];
__device__ __half g_Whi[(size_t)VOCAB * DMODEL];   // fp16 for vocab path
__device__ __half g_Wlo[(size_t)VOCAB * DMODEL];
__device__ __half g_midhi[LSEQ * DMODEL];
__device__ __half g_midlo[LSEQ * DMODEL];
__device__ __nv_bfloat16 g_xhi[LSEQ * DMODEL];
__device__ __nv_bfloat16 g_xlo[LSEQ * DMODEL];
__device__ __nv_bfloat16 g_winhi[2 * DMODEL * DMODEL];
__device__ __nv_bfloat16 g_winlo[2 * DMODEL * DMODEL];
__device__ __nv_bfloat16 g_wdhi[DMODEL * DMODEL];
__device__ __nv_bfloat16 g_wdlo[DMODEL * DMODEL];
__device__ __nv_bfloat16 g_wohi[DMODEL * DMODEL];
__device__ __nv_bfloat16 g_wolo[DMODEL * DMODEL];
__device__ __nv_bfloat16 g_xinhi[LSEQ * DMODEL];
__device__ __nv_bfloat16 g_xinlo[LSEQ * DMODEL];
__device__ __nv_bfloat16 g_lnhi[LSEQ * DMODEL];
__device__ __nv_bfloat16 g_lnlo[LSEQ * DMODEL];

__device__ __forceinline__ uint32_t smem_u32(const void* p) {
  uint32_t a;
  asm("{ .reg .u64 t; cvta.to.shared.u64 t, %1; cvt.u32.u64 %0, t; }"
      : "=r"(a) : "l"(p));
  return a;
}
__device__ __forceinline__ void split2(float v0, float v1,
                                       __nv_bfloat162* hi, __nv_bfloat162* lo) {
  __nv_bfloat16 h0 = __float2bfloat16(v0), h1 = __float2bfloat16(v1);
  __nv_bfloat162 H; H.x = h0; H.y = h1;
  __nv_bfloat162 L;
  L.x = __float2bfloat16(v0 - __bfloat162float(h0));
  L.y = __float2bfloat16(v1 - __bfloat162float(h1));
  *hi = H;
  *lo = L;
}
__device__ __forceinline__ void split2h(float v0, float v1, __half2* hi,
                                        __half2* lo) {
  __half h0 = __float2half_rn(v0), h1 = __float2half_rn(v1);
  *hi = __halves2half2(h0, h1);
  *lo = __halves2half2(__float2half_rn(v0 - __half2float(h0)),
                       __float2half_rn(v1 - __half2float(h1)));
}
#define CP_ASYNC16(dst, src) \
  asm volatile("cp.async.cg.shared.global [%0], [%1], 16;" ::"r"(dst), \
               "l"(src))
#define CP_COMMIT() asm volatile("cp.async.commit_group;")
#define CP_WAIT(n) asm volatile("cp.async.wait_group %0;" ::"n"(n))

// ================= splits =================
__global__ __launch_bounds__(256) void split_kernel(
    const float* __restrict__ src, __nv_bfloat16* __restrict__ hi,
    __nv_bfloat16* __restrict__ lo, int n4) {
  int i = blockIdx.x * 256 + threadIdx.x;
  if (i >= n4) return;
  float4 v = ((const float4*)src)[i];
  float vv[4] = {v.x, v.y, v.z, v.w};
  union { __nv_bfloat16 b[4]; uint2 u; } H, L;
#pragma unroll
  for (int j = 0; j < 4; j++) {
    __nv_bfloat16 h = __float2bfloat16(vv[j]);
    H.b[j] = h;
    L.b[j] = __float2bfloat16(vv[j] - __bfloat162float(h));
  }
  ((uint2*)hi)[i] = H.u;
  ((uint2*)lo)[i] = L.u;
}
__global__ __launch_bounds__(256) void splith_kernel(
    const float* __restrict__ src, __half* __restrict__ hi,
    __half* __restrict__ lo, int n4) {
  int i = blockIdx.x * 256 + threadIdx.x;
  if (i >= n4) return;
  float4 v = ((const float4*)src)[i];
  float vv[4] = {v.x, v.y, v.z, v.w};
  union { __half b[4]; uint2 u; } H, L;
#pragma unroll
  for (int j = 0; j < 4; j++) {
    __half h = __float2half_rn(vv[j]);
    H.b[j] = h;
    L.b[j] = __float2half_rn(vv[j] - __half2float(h));
  }
  ((uint2*)hi)[i] = H.u;
  ((uint2*)lo)[i] = L.u;
}

// ================= split GEMM: mma.sync + ldmatrix + 3-stage cp.async ====
// Block tile 128x128, K-chunk 32, 8 warps (2x4), warp tile 64x32, persistent.
// MODE 0: bf16x3, fp32 out.  MODE 1: bf16x3, xz epilogue.
// MODE 2: bf16x3, softplus transposed.  MODE 3: bf16x3, fp16 hi/lo split out.
// MODE 4: fp16x2 (AhBh + AhBl), fp32 out  [vocab].
// Smem: XOR swizzle chunk^(row&3), tile = 128 rows x 64B, no padding.
#define TILE_B2 8192
#define NCHUNK (DMODEL / 32)

__device__ __forceinline__ void mma_bf16(float* c, const uint32_t* a,
                                         const uint32_t* b) {
  asm volatile(
      "mma.sync.aligned.m16n8k16.row.col.f32.bf16.bf16.f32 "
      "{%0,%1,%2,%3}, {%4,%5,%6,%7}, {%8,%9}, {%0,%1,%2,%3};"
      : "+f"(c[0]), "+f"(c[1]), "+f"(c[2]), "+f"(c[3])
      : "r"(a[0]), "r"(a[1]), "r"(a[2]), "r"(a[3]), "r"(b[0]), "r"(b[1]));
}
__device__ __forceinline__ void mma_f16(float* c, const uint32_t* a,
                                        const uint32_t* b) {
  asm volatile(
      "mma.sync.aligned.m16n8k16.row.col.f32.f16.f16.f32 "
      "{%0,%1,%2,%3}, {%4,%5,%6,%7}, {%8,%9}, {%0,%1,%2,%3};"
      : "+f"(c[0]), "+f"(c[1]), "+f"(c[2]), "+f"(c[3])
      : "r"(a[0]), "r"(a[1]), "r"(a[2]), "r"(a[3]), "r"(b[0]), "r"(b[1]));
}
__device__ __forceinline__ void ldsm_x4(uint32_t* r, uint32_t addr) {
  asm volatile(
      "ldmatrix.sync.aligned.m8n8.x4.shared.b16 {%0,%1,%2,%3}, [%4];"
      : "=r"(r[0]), "=r"(r[1]), "=r"(r[2]), "=r"(r[3]) : "r"(addr));
}
__device__ __forceinline__ void ldsm_x2(uint32_t* r, uint32_t addr) {
  asm volatile(
      "ldmatrix.sync.aligned.m8n8.x2.shared.b16 {%0,%1}, [%2];"
      : "=r"(r[0]), "=r"(r[1]) : "r"(addr));
}

template <int MODE>
__global__ __launch_bounds__(256, 2) void mma_gemm_kernel(
    const void* __restrict__ Ahi_, const void* __restrict__ Alo_,
    const void* __restrict__ Bhi_, const void* __restrict__ Blo_,
    const float* __restrict__ bias, const float* __restrict__ bias2,
    float* __restrict__ out, void* __restrict__ outhi,
    void* __restrict__ outlo, float* __restrict__ out2, int Ncols, int tilesM,
    int nTiles) {
  constexpr int NT = (MODE == 4) ? 3 : 4;
  constexpr int NSLOT = 2 * NT;
  constexpr int STG = NT * TILE_B2;
  const __nv_bfloat16* Ahi = (const __nv_bfloat16*)Ahi_;
  const __nv_bfloat16* Alo = (const __nv_bfloat16*)Alo_;
  const __nv_bfloat16* Bhi = (const __nv_bfloat16*)Bhi_;
  const __nv_bfloat16* Blo = (const __nv_bfloat16*)Blo_;

  extern __shared__ __align__(16) char sm[];
  const uint32_t sbase = smem_u32(sm);
  const int tid = threadIdx.x;
  const int wid = tid >> 5, lane = tid & 31;
  const int wr = wid >> 2, wc = wid & 3;
  const int lr = lane >> 2, lq = lane & 3;
  const int r0 = tid >> 2, q0 = tid & 3;
  const uint32_t pc0 = (uint32_t)((q0 ^ (r0 & 3)) * 16);
  const int ag = lane >> 3, ar8 = lane & 7;
  const int aRow = (ag & 1) * 8 + ar8;
  const int aCH = ag >> 1;
  const int aX = ar8 & 3;
  const int bRow = lane & 7;
  const int bg = (lane >> 3) & 1;
  const int bX = bRow & 3;

  for (int tile = blockIdx.x; tile < nTiles; tile += gridDim.x) {
    const int m0 = (tile % tilesM) * 128;
    const int n0 = (tile / tilesM) * 128;

    float acc[4][4][4];
#pragma unroll
    for (int i = 0; i < 4; i++)
#pragma unroll
      for (int j = 0; j < 4; j++)
#pragma unroll
        for (int q = 0; q < 4; q++) acc[i][j][q] = 0.f;

    const __nv_bfloat16* gp[NSLOT];
    if (MODE == 4) {
      gp[0] = Ahi + (size_t)(m0 + r0) * DMODEL + q0 * 8;
      gp[1] = Ahi + (size_t)(m0 + r0 + 64) * DMODEL + q0 * 8;
      gp[2] = Bhi + (size_t)(n0 + r0) * DMODEL + q0 * 8;
      gp[3] = Bhi + (size_t)(n0 + r0 + 64) * DMODEL + q0 * 8;
      gp[4] = Blo + (size_t)(n0 + r0) * DMODEL + q0 * 8;
      gp[5] = Blo + (size_t)(n0 + r0 + 64) * DMODEL + q0 * 8;
    } else {
      gp[0] = Ahi + (size_t)(m0 + r0) * DMODEL + q0 * 8;
      gp[1] = Ahi + (size_t)(m0 + r0 + 64) * DMODEL + q0 * 8;
      gp[2] = Alo + (size_t)(m0 + r0) * DMODEL + q0 * 8;
      gp[3] = Alo + (size_t)(m0 + r0 + 64) * DMODEL + q0 * 8;
      gp[4] = Bhi + (size_t)(n0 + r0) * DMODEL + q0 * 8;
      gp[5] = Bhi + (size_t)(n0 + r0 + 64) * DMODEL + q0 * 8;
      gp[6] = Blo + (size_t)(n0 + r0) * DMODEL + q0 * 8;
      gp[7] = Blo + (size_t)(n0 + r0 + 64) * DMODEL + q0 * 8;
    }
    uint32_t cpa[NSLOT];
#pragma unroll
    for (int t = 0; t < NSLOT; t++)
      cpa[t] = sbase + (uint32_t)((t >> 1) * TILE_B2 +
                                  (r0 + (t & 1) * 64) * 64) + pc0;

    // prologue: chunks 0,1 -> stages 0,1
#pragma unroll
    for (int t = 0; t < NSLOT; t++) CP_ASYNC16(cpa[t], gp[t]);
    CP_COMMIT();
#pragma unroll
    for (int t = 0; t < NSLOT; t++) CP_ASYNC16(cpa[t] + STG, gp[t] + 32);
    CP_COMMIT();

    int s = 0, sp = 2;
    for (int chunk = 0; chunk < NCHUNK; chunk++) {
      if (chunk < NCHUNK - 1) { CP_WAIT(1); } else { CP_WAIT(0); }
      __syncthreads();
      if (chunk + 2 < NCHUNK) {
        const uint32_t so = (uint32_t)(sp * STG);
        const __nv_bfloat16* off = (const __nv_bfloat16*)0 + (chunk + 2) * 32;
        (void)off;
#pragma unroll
        for (int t = 0; t < NSLOT; t++)
          CP_ASYNC16(cpa[t] + so, gp[t] + (chunk + 2) * 32);
        CP_COMMIT();
        sp = (sp == 2) ? 0 : sp + 1;
      }
      const uint32_t stg = sbase + (uint32_t)(s * STG);
      const uint32_t tAh = stg;
      const uint32_t tAl = stg + TILE_B2;                      // MODE!=4
      const uint32_t tBh = stg + ((MODE == 4) ? 1 : 2) * TILE_B2;
      const uint32_t tBl = stg + ((MODE == 4) ? 2 : 3) * TILE_B2;
#pragma unroll
      for (int half = 0; half < 2; half++) {
        uint32_t bh[4][2], bl[4][2];
#pragma unroll
        for (int j = 0; j < 4; j++) {
          const int row = wc * 32 + j * 8 + bRow;
          const uint32_t co = (uint32_t)((((half * 2 + bg) ^ bX) * 16) +
                                         row * 64);
          ldsm_x2(bh[j], tBh + co);
          ldsm_x2(bl[j], tBl + co);
        }
#pragma unroll
        for (int i = 0; i < 4; i++) {
          const int rowA = wr * 64 + i * 16 + aRow;
          const uint32_t ca = (uint32_t)((((half * 2 + aCH) ^ aX) * 16) +
                                         rowA * 64);
          uint32_t ah[4];
          ldsm_x4(ah, tAh + ca);
          if (MODE == 4) {
#pragma unroll
            for (int j = 0; j < 4; j++) mma_f16(acc[i][j], ah, bh[j]);
#pragma unroll
            for (int j = 0; j < 4; j++) mma_f16(acc[i][j], ah, bl[j]);
          } else {
            uint32_t al[4];
            ldsm_x4(al, tAl + ca);
#pragma unroll
            for (int j = 0; j < 4; j++) mma_bf16(acc[i][j], ah, bh[j]);
#pragma unroll
            for (int j = 0; j < 4; j++) mma_bf16(acc[i][j], ah, bl[j]);
#pragma unroll
            for (int j = 0; j < 4; j++) mma_bf16(acc[i][j], al, bh[j]);
          }
        }
      }
      s = (s == 2) ? 0 : s + 1;
    }
    __syncthreads();  // protect smem before next tile's prologue

    // epilogue
#pragma unroll
    for (int i = 0; i < 4; i++) {
      const int r = m0 + wr * 64 + i * 16 + lr;
#pragma unroll
      for (int j = 0; j < 4; j++) {
        const int c = n0 + wc * 32 + j * 8 + lq * 2;
        const float bx = bias[c], by = bias[c + 1];
        float v00 = acc[i][j][0] + bx, v01 = acc[i][j][1] + by;
        float v10 = acc[i][j][2] + bx, v11 = acc[i][j][3] + by;
        if (MODE == 0 || MODE == 4) {
          *(float2*)(out + (size_t)r * Ncols + c) = make_float2(v00, v01);
          *(float2*)(out + (size_t)(r + 8) * Ncols + c) = make_float2(v10, v11);
        } else if (MODE == 1) {
          if (c < DMODEL) {
            *(float2*)(out + (size_t)r * DMODEL + c) = make_float2(v00, v01);
            *(float2*)(out + (size_t)(r + 8) * DMODEL + c) =
                make_float2(v10, v11);
            split2(v00, v01,
                   (__nv_bfloat162*)((__nv_bfloat16*)outhi + (size_t)r * DMODEL + c),
                   (__nv_bfloat162*)((__nv_bfloat16*)outlo + (size_t)r * DMODEL + c));
            split2(v10, v11,
                   (__nv_bfloat162*)((__nv_bfloat16*)outhi + (size_t)(r + 8) * DMODEL + c),
                   (__nv_bfloat162*)((__nv_bfloat16*)outlo + (size_t)(r + 8) * DMODEL + c));
          } else {
            const int cz = c - DMODEL;
            *(float2*)(out2 + (size_t)r * DMODEL + cz) =
                make_float2(1.f / (1.f + expf(-v00)), 1.f / (1.f + expf(-v01)));
            *(float2*)(out2 + (size_t)(r + 8) * DMODEL + cz) =
                make_float2(1.f / (1.f + expf(-v10)), 1.f / (1.f + expf(-v11)));
          }
        } else if (MODE == 2) {
          v00 += bias2[c];     v01 += bias2[c + 1];
          v10 += bias2[c];     v11 += bias2[c + 1];
          v00 = (v00 > 20.f) ? v00 : log1pf(expf(v00));
          v01 = (v01 > 20.f) ? v01 : log1pf(expf(v01));
          v10 = (v10 > 20.f) ? v10 : log1pf(expf(v10));
          v11 = (v11 > 20.f) ? v11 : log1pf(expf(v11));
          out[(size_t)c * LSEQ + r] = v00;
          out[(size_t)(c + 1) * LSEQ + r] = v01;
          out[(size_t)c * LSEQ + r + 8] = v10;
          out[(size_t)(c + 1) * LSEQ + r + 8] = v11;
        } else {  // MODE 3: fp16 hi/lo split (feeds MODE 4 vocab GEMM)
          split2h(v00, v01,
                  (__half2*)((__half*)outhi + (size_t)r * DMODEL + c),
                  (__half2*)((__half*)outlo + (size_t)r * DMODEL + c));
          split2h(v10, v11,
                  (__half2*)((__half*)outhi + (size_t)(r + 8) * DMODEL + c),
                  (__half2*)((__half*)outlo + (size_t)(r + 8) * DMODEL + c));
        }
      }
    }
  }
}

// ================= B_seq / C_seq =================
__global__ __launch_bounds__(256) void bc_seq_kernel(
    const float* __restrict__ xin, const float* __restrict__ binj,
    const float* __restrict__ cinj, const float* __restrict__ W_B,
    const float* __restrict__ W_C, const float* __restrict__ W_bi,
    const float* __restrict__ W_ci, float* __restrict__ Bseq,
    float* __restrict__ Cseq) {
  __shared__ float sx[DMODEL], sb[DMODEL], sc[DMODEL];
  const int l = blockIdx.x;
  for (int i = threadIdx.x; i < DMODEL; i += 256) {
    sx[i] = xin[(size_t)l * DMODEL + i];
    sb[i] = binj[(size_t)l * DMODEL + i];
    sc[i] = cinj[(size_t)l * DMODEL + i];
  }
  __syncthreads();
  const int n = threadIdx.x >> 3;
  const int part = threadIdx.x & 7;
  float s1 = 0.f, s2 = 0.f, s3 = 0.f, s4 = 0.f;
  const float* wb = W_B + (size_t)n * DMODEL;
  const float* wc = W_C + (size_t)n * DMODEL;
  const float* wbi = W_bi + (size_t)n * DMODEL;
  const float* wci = W_ci + (size_t)n * DMODEL;
#pragma unroll 8
  for (int i = 0; i < 128; i++) {
    int k = part + i * 8;
    float xv = sx[k], bv = sb[k], cv = sc[k];
    s1 = fmaf(xv, wb[k], s1);
    s2 = fmaf(bv, wbi[k], s2);
    s3 = fmaf(xv, wc[k], s3);
    s4 = fmaf(cv, wci[k], s4);
  }
#pragma unroll
  for (int off = 4; off; off >>= 1) {
    s1 += __shfl_down_sync(0xffffffffu, s1, off, 8);
    s2 += __shfl_down_sync(0xffffffffu, s2, off, 8);
    s3 += __shfl_down_sync(0xffffffffu, s3, off, 8);
    s4 += __shfl_down_sync(0xffffffffu, s4, off, 8);
  }
  if (part == 0) {
    Bseq[(size_t)l * NSTATE + n] = s1 * (1.f + tanhf(s2));
    Cseq[(size_t)l * NSTATE + n] = s3 * (1.f + tanhf(s4));
  }
}

// ================= register-resident exact tree scan =================
__global__ __launch_bounds__(512, 1) void fused_scan_kernel(
    const float* __restrict__ log_A, const float* __restrict__ deltaT,
    const float* __restrict__ Bseq, const float* __restrict__ Cseq,
    float* __restrict__ y) {
  __shared__ float smA[8][65], smB[8][65];
  const int tid = threadIdx.x;
  const int d = blockIdx.x >> 2;
  const int n0 = (blockIdx.x & 3) * 8;
  const int col = tid & 7, seg = tid >> 3;
  const int n = n0 + col;
  const int T0 = seg * 32;

  const float S = expf(log_A[d * NSTATE + n]);
  const float invS = 1.f / S;
  const int m = n + 1;
  const bool fast = __syncthreads_and(fabsf(S - (float)m) < 1e-3f);

  float a[32], b[32];
  if (fast) {
    float4 dt4 = *(const float4*)(deltaT + (size_t)d * LSEQ + T0 + col * 4);
    float e[4] = {expf(-dt4.x), expf(-dt4.y), expf(-dt4.z), expf(-dt4.w)};
    const int gb = (tid & 31) & ~7;
#pragma unroll
    for (int j = 0; j < 32; j++) {
      float E = __shfl_sync(0xffffffffu, e[j & 3], gb + (j >> 2), 32);
      float p2 = E * E, p4 = p2 * p2, p8 = p4 * p4, p16 = p8 * p8;
      float r = 1.f;
      if (m & 1) r *= E;
      if (m & 2) r *= p2;
      if (m & 4) r *= p4;
      if (m & 8) r *= p8;
      if (m & 16) r *= p16;
      if (m & 32) r *= p16 * p16;
      a[j] = r;
      b[j] = (1.f - r) * invS * Bseq[(size_t)(T0 + j) * NSTATE + n];
    }
  } else {
#pragma unroll
    for (int j = 0; j < 32; j++) {
      float dt = deltaT[(size_t)d * LSEQ + T0 + j];
      float r = expf(-dt * S);
      a[j] = r;
      b[j] = (1.f - r) * invS * Bseq[(size_t)(T0 + j) * NSTATE + n];
    }
  }

#pragma unroll
  for (int s = 1; s <= 16; s <<= 1)
#pragma unroll
    for (int r = 2 * s - 1; r < 32; r += 2 * s) {
      const int l = r - s;
      float ar = a[r] * a[l];
      b[r] = ar * b[l] + b[r];
      a[r] = ar;
    }

  smA[col][seg] = a[31];
  smB[col][seg] = b[31];
  __syncthreads();
#pragma unroll
  for (int ms = 1; ms < 64; ms <<= 1) {
    int nit = 8 * (64 / (2 * ms));
    if (tid < nit) {
      int c = tid & 7, pr = tid >> 3;
      int l = pr * 2 * ms + ms - 1, r = l + ms;
      float ar = smA[c][r] * smA[c][l];
      smB[c][r] = ar * smB[c][l] + smB[c][r];
      smA[c][r] = ar;
    }
    __syncthreads();
  }
  if (tid < 8) {
    smA[tid][63] = 1.f;
    smB[tid][63] = 0.f;
  }
  __syncthreads();
#pragma unroll
  for (int ms = 32; ms >= 1; ms >>= 1) {
    int nit = 8 * (64 / (2 * ms));
    if (tid < nit) {
      int c = tid & 7, pr = tid >> 3;
      int l = pr * 2 * ms + ms - 1, r = l + ms;
      float al = smA[c][l], bl = smB[c][l];
      float ar = smA[c][r], br = smB[c][r];
      float nb = ar * bl + br;
      smA[c][l] = ar;
      smA[c][r] = ar * al;
      smB[c][l] = nb;
      smB[c][r] = nb;
    }
    __syncthreads();
  }
  a[31] = smA[col][seg];
  b[31] = smB[col][seg];

#pragma unroll
  for (int s = 16; s >= 1; s >>= 1)
#pragma unroll
    for (int r = 2 * s - 1; r < 32; r += 2 * s) {
      const int l = r - s;
      float al = a[l], bl = b[l];
      float ar = a[r], br = b[r];
      float nb = ar * bl + br;
      a[l] = ar;
      a[r] = ar * al;
      b[l] = nb;
      b[r] = nb;
    }

#pragma unroll
  for (int j = 0; j < 32; j++) {
    float v = b[j] * Cseq[(size_t)(T0 + j) * NSTATE + n];
    v += __shfl_xor_sync(0xffffffffu, v, 1, 8);
    v += __shfl_xor_sync(0xffffffffu, v, 2, 8);
    v += __shfl_xor_sync(0xffffffffu, v, 4, 8);
    if (col == 0) atomicAdd(&y[(size_t)(T0 + j) * DMODEL + d], v);
  }
}

// ================= fused u + LayerNorm (emits bf16 hi/lo) =================
__global__ __launch_bounds__(256) void layernorm_kernel(
    const float* __restrict__ y, const float* __restrict__ z,
    const float* __restrict__ xin, const float* __restrict__ g,
    const float* __restrict__ beta, __nv_bfloat16* __restrict__ ohi,
    __nv_bfloat16* __restrict__ olo) {
  const int l = blockIdx.x;
  const size_t base = (size_t)l * DMODEL;
  float uv[4];
  float s = 0.f, s2 = 0.f;
#pragma unroll
  for (int k = 0; k < 2; k++) {
    int i = threadIdx.x * 2 + k * 512;
    float2 yy = *(const float2*)(y + base + i);
    float2 zz = *(const float2*)(z + base + i);
    float2 xx = *(const float2*)(xin + base + i);
    float u0 = fmaf(yy.x, zz.x, xx.x);
    float u1 = fmaf(yy.y, zz.y, xx.y);
    uv[k * 2] = u0;
    uv[k * 2 + 1] = u1;
    s += u0 + u1;
    s2 += u0 * u0 + u1 * u1;
  }
#pragma unroll
  for (int off = 16; off; off >>= 1) {
    s += __shfl_xor_sync(0xffffffffu, s, off);
    s2 += __shfl_xor_sync(0xffffffffu, s2, off);
  }
  __shared__ float shs[8], shs2[8];
  const int w = threadIdx.x >> 5;
  if ((threadIdx.x & 31) == 0) { shs[w] = s; shs2[w] = s2; }
  __syncthreads();
  if (threadIdx.x < 32) {
    s = (threadIdx.x < 8) ? shs[threadIdx.x] : 0.f;
    s2 = (threadIdx.x < 8) ? shs2[threadIdx.x] : 0.f;
#pragma unroll
    for (int off = 4; off; off >>= 1) {
      s += __shfl_xor_sync(0xffffffffu, s, off);
      s2 += __shfl_xor_sync(0xffffffffu, s2, off);
    }
    if (threadIdx.x == 0) { shs[0] = s; shs2[0] = s2; }
  }
  __syncthreads();
  const float mu = shs[0] * (1.f / DMODEL);
  const float var = shs2[0] * (1.f / DMODEL) - mu * mu;
  const float rstd = rsqrtf(var + 1e-5f);
#pragma unroll
  for (int k = 0; k < 2; k++) {
    int i = threadIdx.x * 2 + k * 512;
    float v0 = (uv[k * 2] - mu) * rstd * g[i] + beta[i];
    float v1 = (uv[k * 2 + 1] - mu) * rstd * g[i + 1] + beta[i + 1];
    split2(v0, v1, (__nv_bfloat162*)(ohi + base + i),
           (__nv_bfloat162*)(olo + base + i));
  }
}

// ================= launch =================
extern "C" void kernel_launch(void* const* d_in, const int* in_sizes, int n_in,
                              void* d_out, int out_size) {
  const float* x         = (const float*)d_in[0];
  const float* b_inject  = (const float*)d_in[1];
  const float* c_inject  = (const float*)d_in[2];
  const float* W_in      = (const float*)d_in[3];
  const float* b_in      = (const float*)d_in[4];
  const float* log_A     = (const float*)d_in[5];
  const float* W_B       = (const float*)d_in[6];
  const float* W_C       = (const float*)d_in[7];
  const float* W_delta   = (const float*)d_in[8];
  const float* b_delta   = (const float*)d_in[9];
  const float* delta_bias= (const float*)d_in[10];
  const float* W_bi      = (const float*)d_in[11];
  const float* W_ci      = (const float*)d_in[12];
  const float* ln_g      = (const float*)d_in[13];
  const float* ln_b      = (const float*)d_in[14];
  const float* W_out     = (const float*)d_in[15];
  const float* b_out     = (const float*)d_in[16];
  const float* W_vocab   = (const float*)d_in[17];
  const float* b_vocab   = (const float*)d_in[18];
  float* out = (float*)d_out;

  void* p;
  cudaGetSymbolAddress(&p, g_xin);    float* xin    = (float*)p;
  cudaGetSymbolAddress(&p, g_z);      float* zbuf   = (float*)p;
  cudaGetSymbolAddress(&p, g_deltaT); float* deltaT = (float*)p;
  cudaGetSymbolAddress(&p, g_Bseq);   float* Bseq   = (float*)p;
  cudaGetSymbolAddress(&p, g_Cseq);   float* Cseq   = (float*)p;
  cudaGetSymbolAddress(&p, g_y);      float* ybuf   = (float*)p;
  cudaGetSymbolAddress(&p, g_Whi);    __half* whi   = (__half*)p;
  cudaGetSymbolAddress(&p, g_Wlo);    __half* wlo   = (__half*)p;
  cudaGetSymbolAddress(&p, g_midhi);  __half* mhi   = (__half*)p;
  cudaGetSymbolAddress(&p, g_midlo);  __half* mlo   = (__half*)p;
  cudaGetSymbolAddress(&p, g_xhi);    __nv_bfloat16* xhi  = (__nv_bfloat16*)p;
  cudaGetSymbolAddress(&p, g_xlo);    __nv_bfloat16* xlo  = (__nv_bfloat16*)p;
  cudaGetSymbolAddress(&p, g_winhi);  __nv_bfloat16* winhi= (__nv_bfloat16*)p;
  cudaGetSymbolAddress(&p, g_winlo);  __nv_bfloat16* winlo= (__nv_bfloat16*)p;
  cudaGetSymbolAddress(&p, g_wdhi);   __nv_bfloat16* wdhi = (__nv_bfloat16*)p;
  cudaGetSymbolAddress(&p, g_wdlo);   __nv_bfloat16* wdlo = (__nv_bfloat16*)p;
  cudaGetSymbolAddress(&p, g_wohi);   __nv_bfloat16* wohi = (__nv_bfloat16*)p;
  cudaGetSymbolAddress(&p, g_wolo);   __nv_bfloat16* wolo = (__nv_bfloat16*)p;
  cudaGetSymbolAddress(&p, g_xinhi);  __nv_bfloat16* xinhi= (__nv_bfloat16*)p;
  cudaGetSymbolAddress(&p, g_xinlo);  __nv_bfloat16* xinlo= (__nv_bfloat16*)p;
  cudaGetSymbolAddress(&p, g_lnhi);   __nv_bfloat16* lnhi = (__nv_bfloat16*)p;
  cudaGetSymbolAddress(&p, g_lnlo);   __nv_bfloat16* lnlo = (__nv_bfloat16*)p;

  const int smem_bf = 3 * 4 * TILE_B2;  // 98304
  const int smem_h  = 3 * 3 * TILE_B2;  // 73728
  cudaFuncSetAttribute(mma_gemm_kernel<1>,
                       cudaFuncAttributeMaxDynamicSharedMemorySize, smem_bf);
  cudaFuncSetAttribute(mma_gemm_kernel<2>,
                       cudaFuncAttributeMaxDynamicSharedMemorySize, smem_bf);
  cudaFuncSetAttribute(mma_gemm_kernel<3>,
                       cudaFuncAttributeMaxDynamicSharedMemorySize, smem_bf);
  cudaFuncSetAttribute(mma_gemm_kernel<4>,
                       cudaFuncAttributeMaxDynamicSharedMemorySize, smem_h);

  // 0. static splits
  split_kernel<<<(LSEQ * DMODEL / 4 + 255) / 256, 256>>>(x, xhi, xlo,
                                                         LSEQ * DMODEL / 4);
  split_kernel<<<(2 * DMODEL * DMODEL / 4 + 255) / 256, 256>>>(
      W_in, winhi, winlo, 2 * DMODEL * DMODEL / 4);
  split_kernel<<<(DMODEL * DMODEL / 4 + 255) / 256, 256>>>(
      W_delta, wdhi, wdlo, DMODEL * DMODEL / 4);
  split_kernel<<<(DMODEL * DMODEL / 4 + 255) / 256, 256>>>(
      W_out, wohi, wolo, DMODEL * DMODEL / 4);
  splith_kernel<<<((int)((size_t)VOCAB * DMODEL / 4) + 255) / 256, 256>>>(
      W_vocab, whi, wlo, (int)((size_t)VOCAB * DMODEL / 4));

  const int tM = LSEQ / 128;  // 16
  // 1. xz: xin (fp32 + bf16 split) and z = sigmoid
  mma_gemm_kernel<1><<<tM * (2 * DMODEL / 128), 256, smem_bf>>>(
      xhi, xlo, winhi, winlo, b_in, nullptr, xin, xinhi, xinlo, zbuf,
      2 * DMODEL, tM, tM * (2 * DMODEL / 128));
  // 2. deltaT = softplus(...)^T
  mma_gemm_kernel<2><<<tM * (DMODEL / 128), 256, smem_bf>>>(
      xinhi, xinlo, wdhi, wdlo, b_delta, delta_bias, deltaT, nullptr, nullptr,
      nullptr, DMODEL, tM, tM * (DMODEL / 128));
  // 3. B_seq / C_seq
  bc_seq_kernel<<<LSEQ, 256>>>(xin, b_inject, c_inject, W_B, W_C, W_bi, W_ci,
                               Bseq, Cseq);
  // 4. scan -> y
  cudaMemsetAsync(ybuf, 0, (size_t)LSEQ * DMODEL * sizeof(float));
  fused_scan_kernel<<<DMODEL * 4, 512>>>(log_A, deltaT, Bseq, Cseq, ybuf);
  // 5+6. u fused into LayerNorm -> bf16 split
  layernorm_kernel<<<LSEQ, 256>>>(ybuf, zbuf, xin, ln_g, ln_b, lnhi, lnlo);
  // 7. mid = ln @ W_out^T + b_out  -> fp16 hi/lo split
  mma_gemm_kernel<3><<<tM * (DMODEL / 128), 256, smem_bf>>>(
      lnhi, lnlo, wohi, wolo, b_out, nullptr, nullptr, mhi, mlo, nullptr,
      DMODEL, tM, tM * (DMODEL / 128));
  // 8. logits = mid @ W_vocab^T + b_vocab  (fp16 2-product, persistent)
  mma_gemm_kernel<4><<<296, 256, smem_h>>>(
      mhi, nullptr, whi, wlo, b_vocab, nullptr, out, nullptr, nullptr, nullptr,
      VOCAB, tM, tM * (VOCAB / 128));
}